// round 1
// baseline (speedup 1.0000x reference)
#include <cuda_runtime.h>

#define DIN  256
#define DOUT 128
#define NHEAD 8
#define DH   16

#define MAX_N 50000
#define MAX_E 800000

// Scratch (allocation-free rule: __device__ globals)
__device__ float g_h[MAX_N * DOUT];          // transformed features [N,128]
__device__ float g_alpha_src[MAX_N * NHEAD]; // a1 . h[n,head,:]
__device__ float g_alpha_dst[MAX_N * NHEAD]; // a2 . h[n,head,:]
__device__ float g_denom[MAX_N * NHEAD];     // softmax denominators

// ---------------------------------------------------------------------------
// SGEMM (NT): C[m,n] = sum_k A[m,k] * B[n,k];  A=[M,256], B=[128,256], C=g_h
// Block tile 128x128, K-tile 16, 256 threads, 8x8 per-thread microtile.
// ---------------------------------------------------------------------------
__global__ __launch_bounds__(256) void gemm_nt(const float* __restrict__ A,
                                               const float* __restrict__ B,
                                               int M) {
    const int K = DIN;
    __shared__ float As[16][128 + 4];
    __shared__ float Bs[16][128 + 4];

    int tid = threadIdx.x;          // 0..255
    int blockRow = blockIdx.x * 128;

    int tr = tid / 16;              // 0..15 (M micro-tile)
    int tc = tid % 16;              // 0..15 (N micro-tile)

    int aRow  = tid / 4;            // 0..63 : loads rows aRow, aRow+64
    int aCol4 = tid % 4;            // float4 index within K-tile (16 floats)

    float acc[8][8];
    #pragma unroll
    for (int i = 0; i < 8; i++)
        #pragma unroll
        for (int j = 0; j < 8; j++) acc[i][j] = 0.f;

    for (int k0 = 0; k0 < K; k0 += 16) {
        #pragma unroll
        for (int i = 0; i < 2; i++) {
            int r  = aRow + i * 64;
            int gr = blockRow + r;
            float4 v = make_float4(0.f, 0.f, 0.f, 0.f);
            if (gr < M) v = *reinterpret_cast<const float4*>(&A[(size_t)gr * K + k0 + aCol4 * 4]);
            As[aCol4 * 4 + 0][r] = v.x;
            As[aCol4 * 4 + 1][r] = v.y;
            As[aCol4 * 4 + 2][r] = v.z;
            As[aCol4 * 4 + 3][r] = v.w;
        }
        #pragma unroll
        for (int i = 0; i < 2; i++) {
            int r = aRow + i * 64;   // B row (output column), always < 128
            float4 v = *reinterpret_cast<const float4*>(&B[(size_t)r * K + k0 + aCol4 * 4]);
            Bs[aCol4 * 4 + 0][r] = v.x;
            Bs[aCol4 * 4 + 1][r] = v.y;
            Bs[aCol4 * 4 + 2][r] = v.z;
            Bs[aCol4 * 4 + 3][r] = v.w;
        }
        __syncthreads();

        #pragma unroll
        for (int k = 0; k < 16; k++) {
            float ra[8], rb[8];
            #pragma unroll
            for (int i = 0; i < 8; i++) ra[i] = As[k][tr * 8 + i];
            #pragma unroll
            for (int j = 0; j < 8; j++) rb[j] = Bs[k][tc * 8 + j];
            #pragma unroll
            for (int i = 0; i < 8; i++)
                #pragma unroll
                for (int j = 0; j < 8; j++) acc[i][j] += ra[i] * rb[j];
        }
        __syncthreads();
    }

    #pragma unroll
    for (int i = 0; i < 8; i++) {
        int gr = blockRow + tr * 8 + i;
        if (gr < M) {
            #pragma unroll
            for (int j = 0; j < 8; j++)
                g_h[(size_t)gr * DOUT + tc * 8 + j] = acc[i][j];
        }
    }
}

// ---------------------------------------------------------------------------
// Per-node attention projections + denom zeroing. One thread per (node, head).
// ---------------------------------------------------------------------------
__global__ void alpha_kernel(const float* __restrict__ Watt, int n) {
    int idx = blockIdx.x * blockDim.x + threadIdx.x;
    if (idx >= n * NHEAD) return;
    int node = idx / NHEAD;
    int head = idx % NHEAD;
    const float* hp = &g_h[(size_t)node * DOUT + head * DH];
    float a = 0.f, b = 0.f;
    #pragma unroll
    for (int d = 0; d < DH; d++) {
        float v = hp[d];
        a += v * Watt[d];
        b += v * Watt[DH + d];
    }
    g_alpha_src[idx] = a;
    g_alpha_dst[idx] = b;
    g_denom[idx]     = 0.f;
}

// ---------------------------------------------------------------------------
// Edge scatter: one warp per edge (E real edges + N self loops).
// lane -> 4 consecutive feature dims; head = lane/4.
// num accumulated into d_out via red.global.add.v4.f32, denom via atomicAdd.
// ---------------------------------------------------------------------------
__global__ __launch_bounds__(256) void edge_kernel(const int* __restrict__ ei,
                                                   const float* __restrict__ batt,
                                                   float* __restrict__ out,
                                                   int n, int e) {
    long long g = (long long)blockIdx.x * blockDim.x + threadIdx.x;
    int widx = (int)(g >> 5);
    int lane = (int)(g & 31);
    int total = e + n;
    if (widx >= total) return;

    int src, dst;
    if (widx < e) {
        src = ei[widx];
        dst = ei[e + widx];
    } else {
        src = widx - e;
        dst = src;
    }

    int head = lane >> 2;
    float s = g_alpha_src[src * NHEAD + head] + g_alpha_dst[dst * NHEAD + head] + batt[0];
    s = (s >= 0.f) ? s : 0.2f * s;
    float ev = expf(s);

    if ((lane & 3) == 0)
        atomicAdd(&g_denom[dst * NHEAD + head], ev);

    float4 hv = *reinterpret_cast<const float4*>(&g_h[(size_t)src * DOUT + lane * 4]);
    float* p = &out[(size_t)dst * DOUT + lane * 4];
    asm volatile("red.global.add.v4.f32 [%0], {%1, %2, %3, %4};"
                 :: "l"(p), "f"(hv.x * ev), "f"(hv.y * ev), "f"(hv.z * ev), "f"(hv.w * ev)
                 : "memory");
}

// ---------------------------------------------------------------------------
// out[n, c] /= denom[n, c/16]
// ---------------------------------------------------------------------------
__global__ void finalize_kernel(float* __restrict__ out, int n) {
    int idx = blockIdx.x * blockDim.x + threadIdx.x;
    if (idx >= n * DOUT) return;
    int node = idx / DOUT;
    int head = (idx % DOUT) >> 4;
    out[idx] /= g_denom[node * NHEAD + head];
}

extern "C" void kernel_launch(void* const* d_in, const int* in_sizes, int n_in,
                              void* d_out, int out_size) {
    const float* x    = (const float*)d_in[0];
    const float* Wt   = (const float*)d_in[1];
    const float* Watt = (const float*)d_in[2];
    const float* batt = (const float*)d_in[3];
    const int*   ei   = (const int*)d_in[4];

    int n = in_sizes[0] / DIN;   // 50000
    int e = in_sizes[4] / 2;     // 800000
    float* out = (float*)d_out;

    // 1. h = x @ W^T
    gemm_nt<<<(n + 127) / 128, 256>>>(x, Wt, n);

    // 2. per-node alpha projections (+ zero denom)
    int at = n * NHEAD;
    alpha_kernel<<<(at + 255) / 256, 256>>>(Watt, n);

    // 3. zero numerator accumulator (d_out)
    cudaMemsetAsync(d_out, 0, (size_t)out_size * sizeof(float));

    // 4. edge scatter (E edges + N self loops), warp per edge
    long long threads = (long long)(e + n) * 32;
    edge_kernel<<<(unsigned)((threads + 255) / 256), 256>>>(ei, batt, out, n, e);

    // 5. normalize
    finalize_kernel<<<(n * DOUT + 255) / 256, 256>>>(out, n);
}

// round 2
// speedup vs baseline: 1.2074x; 1.2074x over previous
#include <cuda_runtime.h>

#define DIN  256
#define DOUT 128
#define NHEAD 8
#define DH   16

#define MAX_N 50000
#define MAX_E 800000

// Scratch (allocation-free rule: __device__ globals)
__device__ float g_h[MAX_N * DOUT];          // transformed features [N,128]
__device__ float g_alpha_src[MAX_N * NHEAD]; // a1 . h[n,head,:]
__device__ float g_alpha_dst[MAX_N * NHEAD]; // a2 . h[n,head,:] + b
__device__ int   g_cnt[MAX_N];               // in-degree (excl self loop)
__device__ int   g_row[MAX_N];               // CSR row start
__device__ int   g_cur[MAX_N];               // fill cursor
__device__ int   g_adj[MAX_E];               // src node per (dst-bucketed) edge

// ---------------------------------------------------------------------------
// SGEMM (NT): C[m,n] = sum_k A[m,k] * B[n,k];  A=[M,256], B=[128,256], C=g_h
// ---------------------------------------------------------------------------
__global__ __launch_bounds__(256) void gemm_nt(const float* __restrict__ A,
                                               const float* __restrict__ B,
                                               int M) {
    const int K = DIN;
    __shared__ float As[16][128 + 4];
    __shared__ float Bs[16][128 + 4];

    int tid = threadIdx.x;
    int blockRow = blockIdx.x * 128;
    int tr = tid / 16;
    int tc = tid % 16;
    int aRow  = tid / 4;
    int aCol4 = tid % 4;

    float acc[8][8];
    #pragma unroll
    for (int i = 0; i < 8; i++)
        #pragma unroll
        for (int j = 0; j < 8; j++) acc[i][j] = 0.f;

    for (int k0 = 0; k0 < K; k0 += 16) {
        #pragma unroll
        for (int i = 0; i < 2; i++) {
            int r  = aRow + i * 64;
            int gr = blockRow + r;
            float4 v = make_float4(0.f, 0.f, 0.f, 0.f);
            if (gr < M) v = *reinterpret_cast<const float4*>(&A[(size_t)gr * K + k0 + aCol4 * 4]);
            As[aCol4 * 4 + 0][r] = v.x;
            As[aCol4 * 4 + 1][r] = v.y;
            As[aCol4 * 4 + 2][r] = v.z;
            As[aCol4 * 4 + 3][r] = v.w;
        }
        #pragma unroll
        for (int i = 0; i < 2; i++) {
            int r = aRow + i * 64;
            float4 v = *reinterpret_cast<const float4*>(&B[(size_t)r * K + k0 + aCol4 * 4]);
            Bs[aCol4 * 4 + 0][r] = v.x;
            Bs[aCol4 * 4 + 1][r] = v.y;
            Bs[aCol4 * 4 + 2][r] = v.z;
            Bs[aCol4 * 4 + 3][r] = v.w;
        }
        __syncthreads();

        #pragma unroll
        for (int k = 0; k < 16; k++) {
            float ra[8], rb[8];
            #pragma unroll
            for (int i = 0; i < 8; i++) ra[i] = As[k][tr * 8 + i];
            #pragma unroll
            for (int j = 0; j < 8; j++) rb[j] = Bs[k][tc * 8 + j];
            #pragma unroll
            for (int i = 0; i < 8; i++)
                #pragma unroll
                for (int j = 0; j < 8; j++) acc[i][j] += ra[i] * rb[j];
        }
        __syncthreads();
    }

    #pragma unroll
    for (int i = 0; i < 8; i++) {
        int gr = blockRow + tr * 8 + i;
        if (gr < M) {
            #pragma unroll
            for (int j = 0; j < 8; j++)
                g_h[(size_t)gr * DOUT + tc * 8 + j] = acc[i][j];
        }
    }
}

// ---------------------------------------------------------------------------
// CSR build: zero counts, histogram over dst, exclusive scan, cursor fill
// ---------------------------------------------------------------------------
__global__ void zero_cnt_kernel(int n) {
    int i = blockIdx.x * blockDim.x + threadIdx.x;
    if (i < n) g_cnt[i] = 0;
}

__global__ void hist_kernel(const int* __restrict__ ei, int e) {
    int i = blockIdx.x * blockDim.x + threadIdx.x;
    if (i < e) atomicAdd(&g_cnt[ei[e + i]], 1);   // dst = ei[1] row
}

// Single-block exclusive scan over g_cnt[0..n) -> g_row, g_cur
__global__ __launch_bounds__(1024) void scan_kernel(int n) {
    __shared__ int warp_sums[32];
    int tid  = threadIdx.x;
    int lane = tid & 31;
    int wid  = tid >> 5;
    int carry = 0;

    for (int base = 0; base < n; base += 1024) {
        int i = base + tid;
        int v = (i < n) ? g_cnt[i] : 0;
        // inclusive warp scan
        int x = v;
        #pragma unroll
        for (int o = 1; o < 32; o <<= 1) {
            int y = __shfl_up_sync(0xffffffffu, x, o);
            if (lane >= o) x += y;
        }
        if (lane == 31) warp_sums[wid] = x;
        __syncthreads();
        if (wid == 0) {
            int s = warp_sums[lane];
            #pragma unroll
            for (int o = 1; o < 32; o <<= 1) {
                int y = __shfl_up_sync(0xffffffffu, s, o);
                if (lane >= o) s += y;
            }
            warp_sums[lane] = s;
        }
        __syncthreads();
        int excl = x - v + ((wid > 0) ? warp_sums[wid - 1] : 0) + carry;
        if (i < n) { g_row[i] = excl; g_cur[i] = excl; }
        int btot = warp_sums[31];
        __syncthreads();   // protect warp_sums before next iteration
        carry += btot;
    }
}

__global__ void fill_kernel(const int* __restrict__ ei, int e) {
    int i = blockIdx.x * blockDim.x + threadIdx.x;
    if (i >= e) return;
    int src = ei[i];
    int dst = ei[e + i];
    int pos = atomicAdd(&g_cur[dst], 1);
    g_adj[pos] = src;
}

// ---------------------------------------------------------------------------
// Per-node attention projections (b_att folded into alpha_dst).
// ---------------------------------------------------------------------------
__global__ void alpha_kernel(const float* __restrict__ Watt,
                             const float* __restrict__ batt, int n) {
    int idx = blockIdx.x * blockDim.x + threadIdx.x;
    if (idx >= n * NHEAD) return;
    int node = idx / NHEAD;
    int head = idx % NHEAD;
    const float* hp = &g_h[(size_t)node * DOUT + head * DH];
    float a = 0.f, b = batt[0];
    #pragma unroll
    for (int d = 0; d < DH; d++) {
        float v = hp[d];
        a += v * Watt[d];
        b += v * Watt[DH + d];
    }
    g_alpha_src[idx] = a;
    g_alpha_dst[idx] = b;
}

// ---------------------------------------------------------------------------
// Gather: one warp per dst node. Register accumulation, local denominator,
// fused normalize + store. No atomics anywhere.
// lane -> feature dims [lane*4, lane*4+4), head = lane/4.
// ---------------------------------------------------------------------------
__global__ __launch_bounds__(256) void gather_kernel(float* __restrict__ out, int n) {
    int w = (blockIdx.x * blockDim.x + threadIdx.x) >> 5;
    if (w >= n) return;
    int lane = threadIdx.x & 31;
    int head = lane >> 2;

    int start = g_row[w];
    int deg   = g_cnt[w];

    float adst = g_alpha_dst[w * NHEAD + head];

    // self loop
    float s0 = g_alpha_src[w * NHEAD + head] + adst;
    s0 = (s0 >= 0.f) ? s0 : 0.2f * s0;
    float ev = __expf(s0);
    float denom = ev;
    float4 hv = *reinterpret_cast<const float4*>(&g_h[(size_t)w * DOUT + lane * 4]);
    float4 acc = make_float4(hv.x * ev, hv.y * ev, hv.z * ev, hv.w * ev);

    #pragma unroll 4
    for (int j = 0; j < deg; j++) {
        int src = __ldg(&g_adj[start + j]);
        float s = g_alpha_src[src * NHEAD + head] + adst;
        s = (s >= 0.f) ? s : 0.2f * s;
        float e2 = __expf(s);
        denom += e2;
        float4 v = *reinterpret_cast<const float4*>(&g_h[(size_t)src * DOUT + lane * 4]);
        acc.x += e2 * v.x;
        acc.y += e2 * v.y;
        acc.z += e2 * v.z;
        acc.w += e2 * v.w;
    }

    float inv = 1.f / denom;
    float4 r = make_float4(acc.x * inv, acc.y * inv, acc.z * inv, acc.w * inv);
    *reinterpret_cast<float4*>(&out[(size_t)w * DOUT + lane * 4]) = r;
}

extern "C" void kernel_launch(void* const* d_in, const int* in_sizes, int n_in,
                              void* d_out, int out_size) {
    const float* x    = (const float*)d_in[0];
    const float* Wt   = (const float*)d_in[1];
    const float* Watt = (const float*)d_in[2];
    const float* batt = (const float*)d_in[3];
    const int*   ei   = (const int*)d_in[4];

    int n = in_sizes[0] / DIN;   // 50000
    int e = in_sizes[4] / 2;     // 800000
    float* out = (float*)d_out;

    // CSR build (independent of GEMM, same stream)
    zero_cnt_kernel<<<(n + 255) / 256, 256>>>(n);
    hist_kernel<<<(e + 255) / 256, 256>>>(ei, e);
    scan_kernel<<<1, 1024>>>(n);
    fill_kernel<<<(e + 255) / 256, 256>>>(ei, e);

    // h = x @ W^T, then per-node attention projections
    gemm_nt<<<(n + 127) / 128, 256>>>(x, Wt, n);
    int at = n * NHEAD;
    alpha_kernel<<<(at + 255) / 256, 256>>>(Watt, batt, n);

    // Gather + softmax + normalize, fused
    long long threads = (long long)n * 32;
    gather_kernel<<<(unsigned)((threads + 255) / 256), 256>>>(out, n);
}

// round 3
// speedup vs baseline: 1.4446x; 1.1964x over previous
#include <cuda_runtime.h>
#include <cstdint>

#define DIN  256
#define DOUT 128
#define NHEAD 8
#define DH   16

#define MAX_N 50000
#define MAX_E 800000

__device__ float g_h[MAX_N * DOUT];
__device__ float g_alpha_src[MAX_N * NHEAD];
__device__ float g_alpha_dst[MAX_N * NHEAD];
__device__ int   g_cnt[MAX_N];
__device__ int   g_row[MAX_N];
__device__ int   g_cur[MAX_N];
__device__ int   g_adj[MAX_E];
__device__ int   g_bsum[1024];

// ---------------------------------------------------------------------------
// tf32 helpers
// ---------------------------------------------------------------------------
__device__ __forceinline__ float tf32r(float x) {
    float y;
    asm("cvt.rna.tf32.f32 %0, %1;" : "=f"(y) : "f"(x));
    return y;
}

#define MMA_TF32(C, A, B)                                                     \
    asm volatile("mma.sync.aligned.m16n8k8.row.col.f32.tf32.tf32.f32 "        \
                 "{%0,%1,%2,%3}, {%4,%5,%6,%7}, {%8,%9}, {%0,%1,%2,%3};"      \
                 : "+f"((C)[0]), "+f"((C)[1]), "+f"((C)[2]), "+f"((C)[3])     \
                 : "r"((A)[0]), "r"((A)[1]), "r"((A)[2]), "r"((A)[3]),        \
                   "r"((B)[0]), "r"((B)[1]))

// ---------------------------------------------------------------------------
// 3xTF32 GEMM (NT): g_h[m,n] = sum_k A[m,k]*B[n,k]; A=[M,256], B=[128,256]
// Block: 128(M) x 128(N), K-tile 16, 256 threads = 8 warps (2M x 4N),
// warp tile 64x32 -> 4x4 m16n8k8 tiles. hi/lo split for fp32-class accuracy.
// ---------------------------------------------------------------------------
#define KT 16
#define SPAD 136
__global__ __launch_bounds__(256) void gemm_tf32(const float* __restrict__ A,
                                                 const float* __restrict__ B,
                                                 int M) {
    __shared__ float As_hi[KT][SPAD], As_lo[KT][SPAD];
    __shared__ float Bs_hi[KT][SPAD], Bs_lo[KT][SPAD];

    int tid = threadIdx.x;
    int blockRow = blockIdx.x * 128;
    int warpId = tid >> 5, lane = tid & 31;
    int g = lane >> 2, tig = lane & 3;
    int mBase = (warpId & 1) * 64;
    int nBase = (warpId >> 1) * 32;

    float c[4][4][4];
    #pragma unroll
    for (int mt = 0; mt < 4; mt++)
        #pragma unroll
        for (int nt = 0; nt < 4; nt++)
            #pragma unroll
            for (int r = 0; r < 4; r++) c[mt][nt][r] = 0.f;

    int lm = tid & 127;            // loader row (m for A, n for B)
    int lk = (tid >> 7) * 8;       // loader k offset within tile
    int gm = blockRow + lm;
    if (gm > M - 1) gm = M - 1;    // clamp (stores are guarded)

    for (int k0 = 0; k0 < DIN; k0 += KT) {
        #pragma unroll
        for (int q = 0; q < 2; q++) {
            float4 va = *reinterpret_cast<const float4*>(&A[(size_t)gm * DIN + k0 + lk + q * 4]);
            float4 vb = *reinterpret_cast<const float4*>(&B[(size_t)lm * DIN + k0 + lk + q * 4]);
            float av[4] = {va.x, va.y, va.z, va.w};
            float bv[4] = {vb.x, vb.y, vb.z, vb.w};
            #pragma unroll
            for (int j = 0; j < 4; j++) {
                int kk = lk + q * 4 + j;
                float ah = tf32r(av[j]);
                As_hi[kk][lm] = ah;
                As_lo[kk][lm] = tf32r(av[j] - ah);
                float bh = tf32r(bv[j]);
                Bs_hi[kk][lm] = bh;
                Bs_lo[kk][lm] = tf32r(bv[j] - bh);
            }
        }
        __syncthreads();

        #pragma unroll
        for (int kk = 0; kk < KT; kk += 8) {
            uint32_t a_hi[4][4], a_lo[4][4], b_hi[4][2], b_lo[4][2];
            #pragma unroll
            for (int mt = 0; mt < 4; mt++) {
                int m0 = mBase + mt * 16 + g;
                a_hi[mt][0] = __float_as_uint(As_hi[kk + tig][m0]);
                a_hi[mt][1] = __float_as_uint(As_hi[kk + tig][m0 + 8]);
                a_hi[mt][2] = __float_as_uint(As_hi[kk + tig + 4][m0]);
                a_hi[mt][3] = __float_as_uint(As_hi[kk + tig + 4][m0 + 8]);
                a_lo[mt][0] = __float_as_uint(As_lo[kk + tig][m0]);
                a_lo[mt][1] = __float_as_uint(As_lo[kk + tig][m0 + 8]);
                a_lo[mt][2] = __float_as_uint(As_lo[kk + tig + 4][m0]);
                a_lo[mt][3] = __float_as_uint(As_lo[kk + tig + 4][m0 + 8]);
            }
            #pragma unroll
            for (int nt = 0; nt < 4; nt++) {
                int n0 = nBase + nt * 8 + g;
                b_hi[nt][0] = __float_as_uint(Bs_hi[kk + tig][n0]);
                b_hi[nt][1] = __float_as_uint(Bs_hi[kk + tig + 4][n0]);
                b_lo[nt][0] = __float_as_uint(Bs_lo[kk + tig][n0]);
                b_lo[nt][1] = __float_as_uint(Bs_lo[kk + tig + 4][n0]);
            }
            #pragma unroll
            for (int mt = 0; mt < 4; mt++)
                #pragma unroll
                for (int nt = 0; nt < 4; nt++) {
                    MMA_TF32(c[mt][nt], a_hi[mt], b_hi[nt]);
                    MMA_TF32(c[mt][nt], a_lo[mt], b_hi[nt]);
                    MMA_TF32(c[mt][nt], a_hi[mt], b_lo[nt]);
                }
        }
        __syncthreads();
    }

    #pragma unroll
    for (int mt = 0; mt < 4; mt++) {
        int row0 = blockRow + mBase + mt * 16 + g;
        int row1 = row0 + 8;
        #pragma unroll
        for (int nt = 0; nt < 4; nt++) {
            int col = nBase + nt * 8 + tig * 2;
            if (row0 < M)
                *reinterpret_cast<float2*>(&g_h[(size_t)row0 * DOUT + col]) =
                    make_float2(c[mt][nt][0], c[mt][nt][1]);
            if (row1 < M)
                *reinterpret_cast<float2*>(&g_h[(size_t)row1 * DOUT + col]) =
                    make_float2(c[mt][nt][2], c[mt][nt][3]);
        }
    }
}

// ---------------------------------------------------------------------------
// CSR build
// ---------------------------------------------------------------------------
__global__ void hist_kernel(const int* __restrict__ ei, int e) {
    int i0 = (blockIdx.x * blockDim.x + threadIdx.x) * 4;
    if (i0 + 3 < e) {
        int4 d = *reinterpret_cast<const int4*>(&ei[e + i0]);
        atomicAdd(&g_cnt[d.x], 1);
        atomicAdd(&g_cnt[d.y], 1);
        atomicAdd(&g_cnt[d.z], 1);
        atomicAdd(&g_cnt[d.w], 1);
    } else {
        for (int i = i0; i < e; i++) atomicAdd(&g_cnt[ei[e + i]], 1);
    }
}

// pass 1: per-block sums of g_cnt
__global__ __launch_bounds__(256) void scan1_kernel(int n) {
    __shared__ int ws[8];
    int i = blockIdx.x * 256 + threadIdx.x;
    int v = (i < n) ? g_cnt[i] : 0;
    int lane = threadIdx.x & 31, wid = threadIdx.x >> 5;
    int s = v;
    #pragma unroll
    for (int o = 16; o > 0; o >>= 1) s += __shfl_down_sync(0xffffffffu, s, o);
    if (lane == 0) ws[wid] = s;
    __syncthreads();
    if (threadIdx.x == 0) {
        int t = 0;
        #pragma unroll
        for (int w = 0; w < 8; w++) t += ws[w];
        g_bsum[blockIdx.x] = t;
    }
}

// pass 2: exclusive scan of block sums (single block)
__global__ __launch_bounds__(1024) void scan2_kernel(int nb) {
    __shared__ int sh[1024];
    int t = threadIdx.x;
    int v = (t < nb) ? g_bsum[t] : 0;
    sh[t] = v;
    __syncthreads();
    for (int o = 1; o < 1024; o <<= 1) {
        int y = (t >= o) ? sh[t - o] : 0;
        __syncthreads();
        sh[t] += y;
        __syncthreads();
    }
    if (t < nb) g_bsum[t] = sh[t] - v;   // exclusive
}

// pass 3: local exclusive scan + block offset -> g_row, g_cur
__global__ __launch_bounds__(256) void scan3_kernel(int n) {
    __shared__ int ws[8];
    int i = blockIdx.x * 256 + threadIdx.x;
    int v = (i < n) ? g_cnt[i] : 0;
    int lane = threadIdx.x & 31, wid = threadIdx.x >> 5;
    int x = v;
    #pragma unroll
    for (int o = 1; o < 32; o <<= 1) {
        int y = __shfl_up_sync(0xffffffffu, x, o);
        if (lane >= o) x += y;
    }
    if (lane == 31) ws[wid] = x;
    __syncthreads();
    if (wid == 0 && lane < 8) {
        int s = ws[lane];
        #pragma unroll
        for (int o = 1; o < 8; o <<= 1) {
            int y = __shfl_up_sync(0xffu, s, o);
            if (lane >= o) s += y;
        }
        ws[lane] = s;
    }
    __syncthreads();
    int excl = x - v + ((wid > 0) ? ws[wid - 1] : 0) + g_bsum[blockIdx.x];
    if (i < n) { g_row[i] = excl; g_cur[i] = excl; }
}

__global__ void fill_kernel(const int* __restrict__ ei, int e) {
    int i0 = (blockIdx.x * blockDim.x + threadIdx.x) * 4;
    if (i0 + 3 < e) {
        int4 s = *reinterpret_cast<const int4*>(&ei[i0]);
        int4 d = *reinterpret_cast<const int4*>(&ei[e + i0]);
        int p0 = atomicAdd(&g_cur[d.x], 1);
        int p1 = atomicAdd(&g_cur[d.y], 1);
        int p2 = atomicAdd(&g_cur[d.z], 1);
        int p3 = atomicAdd(&g_cur[d.w], 1);
        g_adj[p0] = s.x; g_adj[p1] = s.y; g_adj[p2] = s.z; g_adj[p3] = s.w;
    } else {
        for (int i = i0; i < e; i++) {
            int pos = atomicAdd(&g_cur[ei[e + i]], 1);
            g_adj[pos] = ei[i];
        }
    }
}

// ---------------------------------------------------------------------------
// Per-node attention projections (b folded into alpha_dst)
// ---------------------------------------------------------------------------
__global__ void alpha_kernel(const float* __restrict__ Watt,
                             const float* __restrict__ batt, int n) {
    int idx = blockIdx.x * blockDim.x + threadIdx.x;
    if (idx >= n * NHEAD) return;
    int node = idx / NHEAD;
    int head = idx % NHEAD;
    const float* hp = &g_h[(size_t)node * DOUT + head * DH];
    float a = 0.f, b = batt[0];
    #pragma unroll
    for (int d = 0; d < DH; d++) {
        float v = hp[d];
        a += v * Watt[d];
        b += v * Watt[DH + d];
    }
    g_alpha_src[idx] = a;
    g_alpha_dst[idx] = b;
}

// ---------------------------------------------------------------------------
// Gather: warp per dst node, register softmax-weighted accumulation, no atomics
// ---------------------------------------------------------------------------
__global__ __launch_bounds__(256) void gather_kernel(float* __restrict__ out, int n) {
    int w = (blockIdx.x * blockDim.x + threadIdx.x) >> 5;
    if (w >= n) return;
    int lane = threadIdx.x & 31;
    int head = lane >> 2;

    int start = g_row[w];
    int deg   = g_cnt[w];
    float adst = g_alpha_dst[w * NHEAD + head];

    float s0 = g_alpha_src[w * NHEAD + head] + adst;
    s0 = (s0 >= 0.f) ? s0 : 0.2f * s0;
    float ev = __expf(s0);
    float denom = ev;
    float4 hv = *reinterpret_cast<const float4*>(&g_h[(size_t)w * DOUT + lane * 4]);
    float4 acc = make_float4(hv.x * ev, hv.y * ev, hv.z * ev, hv.w * ev);

    #pragma unroll 4
    for (int j = 0; j < deg; j++) {
        int src = __ldg(&g_adj[start + j]);
        float s = g_alpha_src[src * NHEAD + head] + adst;
        s = (s >= 0.f) ? s : 0.2f * s;
        float e2 = __expf(s);
        denom += e2;
        float4 v = *reinterpret_cast<const float4*>(&g_h[(size_t)src * DOUT + lane * 4]);
        acc.x += e2 * v.x;
        acc.y += e2 * v.y;
        acc.z += e2 * v.z;
        acc.w += e2 * v.w;
    }

    float inv = 1.f / denom;
    *reinterpret_cast<float4*>(&out[(size_t)w * DOUT + lane * 4]) =
        make_float4(acc.x * inv, acc.y * inv, acc.z * inv, acc.w * inv);
}

extern "C" void kernel_launch(void* const* d_in, const int* in_sizes, int n_in,
                              void* d_out, int out_size) {
    const float* x    = (const float*)d_in[0];
    const float* Wt   = (const float*)d_in[1];
    const float* Watt = (const float*)d_in[2];
    const float* batt = (const float*)d_in[3];
    const int*   ei   = (const int*)d_in[4];

    int n = in_sizes[0] / DIN;   // 50000
    int e = in_sizes[4] / 2;     // 800000
    float* out = (float*)d_out;

    // CSR build
    void* cntp = nullptr;
    cudaGetSymbolAddress(&cntp, g_cnt);
    cudaMemsetAsync(cntp, 0, (size_t)n * sizeof(int));
    int et = (e + 3) / 4;
    hist_kernel<<<(et + 255) / 256, 256>>>(ei, e);
    int nb = (n + 255) / 256;
    scan1_kernel<<<nb, 256>>>(n);
    scan2_kernel<<<1, 1024>>>(nb);
    scan3_kernel<<<nb, 256>>>(n);
    fill_kernel<<<(et + 255) / 256, 256>>>(ei, e);

    // h = x @ W^T (3xTF32 tensor core)
    gemm_tf32<<<(n + 127) / 128, 256>>>(x, Wt, n);
    int at = n * NHEAD;
    alpha_kernel<<<(at + 255) / 256, 256>>>(Watt, batt, n);

    // fused gather + softmax + normalize
    long long threads = (long long)n * 32;
    gather_kernel<<<(unsigned)((threads + 255) / 256), 256>>>(out, n);
}

// round 4
// speedup vs baseline: 1.4453x; 1.0005x over previous
#include <cuda_runtime.h>
#include <cstdint>

#define DIN  256
#define DOUT 128
#define NHEAD 8
#define DH   16

#define MAX_N 50000
#define MAX_E 800000

__device__ float g_h[MAX_N * DOUT];
__device__ float g_alpha_src[MAX_N * NHEAD];
__device__ float g_alpha_dst[MAX_N * NHEAD];
__device__ int   g_cnt[MAX_N];
__device__ int   g_row[MAX_N];
__device__ int   g_cur[MAX_N];
__device__ int   g_adj[MAX_E];
__device__ int   g_bsum[1024];

// ---------------------------------------------------------------------------
// tf32 helpers
// ---------------------------------------------------------------------------
__device__ __forceinline__ float tf32r(float x) {
    float y;
    asm("cvt.rna.tf32.f32 %0, %1;" : "=f"(y) : "f"(x));
    return y;
}

#define MMA_TF32(C, A, B)                                                     \
    asm volatile("mma.sync.aligned.m16n8k8.row.col.f32.tf32.tf32.f32 "        \
                 "{%0,%1,%2,%3}, {%4,%5,%6,%7}, {%8,%9}, {%0,%1,%2,%3};"      \
                 : "+f"((C)[0]), "+f"((C)[1]), "+f"((C)[2]), "+f"((C)[3])     \
                 : "r"((A)[0]), "r"((A)[1]), "r"((A)[2]), "r"((A)[3]),        \
                   "r"((B)[0]), "r"((B)[1]))

// ---------------------------------------------------------------------------
// 3xTF32 GEMM (NT): g_h[m,n] = sum_k A[m,k]*B[n,k]; A=[M,256], B=[128,256]
// Block: 128(M) x 128(N), K-tile 16, 256 threads = 8 warps (2M x 4N),
// warp tile 64x32 -> 4x4 m16n8k8 tiles. hi/lo split for fp32-class accuracy.
// ---------------------------------------------------------------------------
#define KT 16
#define SPAD 136
__global__ __launch_bounds__(256) void gemm_tf32(const float* __restrict__ A,
                                                 const float* __restrict__ B,
                                                 int M) {
    __shared__ float As_hi[KT][SPAD], As_lo[KT][SPAD];
    __shared__ float Bs_hi[KT][SPAD], Bs_lo[KT][SPAD];

    int tid = threadIdx.x;
    int blockRow = blockIdx.x * 128;
    int warpId = tid >> 5, lane = tid & 31;
    int g = lane >> 2, tig = lane & 3;
    int mBase = (warpId & 1) * 64;
    int nBase = (warpId >> 1) * 32;

    float c[4][4][4];
    #pragma unroll
    for (int mt = 0; mt < 4; mt++)
        #pragma unroll
        for (int nt = 0; nt < 4; nt++)
            #pragma unroll
            for (int r = 0; r < 4; r++) c[mt][nt][r] = 0.f;

    int lm = tid & 127;            // loader row (m for A, n for B)
    int lk = (tid >> 7) * 8;       // loader k offset within tile
    int gm = blockRow + lm;
    if (gm > M - 1) gm = M - 1;    // clamp (stores are guarded)

    for (int k0 = 0; k0 < DIN; k0 += KT) {
        #pragma unroll
        for (int q = 0; q < 2; q++) {
            float4 va = *reinterpret_cast<const float4*>(&A[(size_t)gm * DIN + k0 + lk + q * 4]);
            float4 vb = *reinterpret_cast<const float4*>(&B[(size_t)lm * DIN + k0 + lk + q * 4]);
            float av[4] = {va.x, va.y, va.z, va.w};
            float bv[4] = {vb.x, vb.y, vb.z, vb.w};
            #pragma unroll
            for (int j = 0; j < 4; j++) {
                int kk = lk + q * 4 + j;
                float ah = tf32r(av[j]);
                As_hi[kk][lm] = ah;
                As_lo[kk][lm] = tf32r(av[j] - ah);
                float bh = tf32r(bv[j]);
                Bs_hi[kk][lm] = bh;
                Bs_lo[kk][lm] = tf32r(bv[j] - bh);
            }
        }
        __syncthreads();

        #pragma unroll
        for (int kk = 0; kk < KT; kk += 8) {
            uint32_t a_hi[4][4], a_lo[4][4], b_hi[4][2], b_lo[4][2];
            #pragma unroll
            for (int mt = 0; mt < 4; mt++) {
                int m0 = mBase + mt * 16 + g;
                a_hi[mt][0] = __float_as_uint(As_hi[kk + tig][m0]);
                a_hi[mt][1] = __float_as_uint(As_hi[kk + tig][m0 + 8]);
                a_hi[mt][2] = __float_as_uint(As_hi[kk + tig + 4][m0]);
                a_hi[mt][3] = __float_as_uint(As_hi[kk + tig + 4][m0 + 8]);
                a_lo[mt][0] = __float_as_uint(As_lo[kk + tig][m0]);
                a_lo[mt][1] = __float_as_uint(As_lo[kk + tig][m0 + 8]);
                a_lo[mt][2] = __float_as_uint(As_lo[kk + tig + 4][m0]);
                a_lo[mt][3] = __float_as_uint(As_lo[kk + tig + 4][m0 + 8]);
            }
            #pragma unroll
            for (int nt = 0; nt < 4; nt++) {
                int n0 = nBase + nt * 8 + g;
                b_hi[nt][0] = __float_as_uint(Bs_hi[kk + tig][n0]);
                b_hi[nt][1] = __float_as_uint(Bs_hi[kk + tig + 4][n0]);
                b_lo[nt][0] = __float_as_uint(Bs_lo[kk + tig][n0]);
                b_lo[nt][1] = __float_as_uint(Bs_lo[kk + tig + 4][n0]);
            }
            #pragma unroll
            for (int mt = 0; mt < 4; mt++)
                #pragma unroll
                for (int nt = 0; nt < 4; nt++) {
                    MMA_TF32(c[mt][nt], a_hi[mt], b_hi[nt]);
                    MMA_TF32(c[mt][nt], a_lo[mt], b_hi[nt]);
                    MMA_TF32(c[mt][nt], a_hi[mt], b_lo[nt]);
                }
        }
        __syncthreads();
    }

    #pragma unroll
    for (int mt = 0; mt < 4; mt++) {
        int row0 = blockRow + mBase + mt * 16 + g;
        int row1 = row0 + 8;
        #pragma unroll
        for (int nt = 0; nt < 4; nt++) {
            int col = nBase + nt * 8 + tig * 2;
            if (row0 < M)
                *reinterpret_cast<float2*>(&g_h[(size_t)row0 * DOUT + col]) =
                    make_float2(c[mt][nt][0], c[mt][nt][1]);
            if (row1 < M)
                *reinterpret_cast<float2*>(&g_h[(size_t)row1 * DOUT + col]) =
                    make_float2(c[mt][nt][2], c[mt][nt][3]);
        }
    }
}

// ---------------------------------------------------------------------------
// CSR build
// ---------------------------------------------------------------------------
__global__ void hist_kernel(const int* __restrict__ ei, int e) {
    int i0 = (blockIdx.x * blockDim.x + threadIdx.x) * 4;
    if (i0 + 3 < e) {
        int4 d = *reinterpret_cast<const int4*>(&ei[e + i0]);
        atomicAdd(&g_cnt[d.x], 1);
        atomicAdd(&g_cnt[d.y], 1);
        atomicAdd(&g_cnt[d.z], 1);
        atomicAdd(&g_cnt[d.w], 1);
    } else {
        for (int i = i0; i < e; i++) atomicAdd(&g_cnt[ei[e + i]], 1);
    }
}

// pass 1: per-block sums of g_cnt
__global__ __launch_bounds__(256) void scan1_kernel(int n) {
    __shared__ int ws[8];
    int i = blockIdx.x * 256 + threadIdx.x;
    int v = (i < n) ? g_cnt[i] : 0;
    int lane = threadIdx.x & 31, wid = threadIdx.x >> 5;
    int s = v;
    #pragma unroll
    for (int o = 16; o > 0; o >>= 1) s += __shfl_down_sync(0xffffffffu, s, o);
    if (lane == 0) ws[wid] = s;
    __syncthreads();
    if (threadIdx.x == 0) {
        int t = 0;
        #pragma unroll
        for (int w = 0; w < 8; w++) t += ws[w];
        g_bsum[blockIdx.x] = t;
    }
}

// pass 2: exclusive scan of block sums (single block)
__global__ __launch_bounds__(1024) void scan2_kernel(int nb) {
    __shared__ int sh[1024];
    int t = threadIdx.x;
    int v = (t < nb) ? g_bsum[t] : 0;
    sh[t] = v;
    __syncthreads();
    for (int o = 1; o < 1024; o <<= 1) {
        int y = (t >= o) ? sh[t - o] : 0;
        __syncthreads();
        sh[t] += y;
        __syncthreads();
    }
    if (t < nb) g_bsum[t] = sh[t] - v;   // exclusive
}

// pass 3: local exclusive scan + block offset -> g_row, g_cur
__global__ __launch_bounds__(256) void scan3_kernel(int n) {
    __shared__ int ws[8];
    int i = blockIdx.x * 256 + threadIdx.x;
    int v = (i < n) ? g_cnt[i] : 0;
    int lane = threadIdx.x & 31, wid = threadIdx.x >> 5;
    int x = v;
    #pragma unroll
    for (int o = 1; o < 32; o <<= 1) {
        int y = __shfl_up_sync(0xffffffffu, x, o);
        if (lane >= o) x += y;
    }
    if (lane == 31) ws[wid] = x;
    __syncthreads();
    if (wid == 0 && lane < 8) {
        int s = ws[lane];
        #pragma unroll
        for (int o = 1; o < 8; o <<= 1) {
            int y = __shfl_up_sync(0xffu, s, o);
            if (lane >= o) s += y;
        }
        ws[lane] = s;
    }
    __syncthreads();
    int excl = x - v + ((wid > 0) ? ws[wid - 1] : 0) + g_bsum[blockIdx.x];
    if (i < n) { g_row[i] = excl; g_cur[i] = excl; }
}

__global__ void fill_kernel(const int* __restrict__ ei, int e) {
    int i0 = (blockIdx.x * blockDim.x + threadIdx.x) * 4;
    if (i0 + 3 < e) {
        int4 s = *reinterpret_cast<const int4*>(&ei[i0]);
        int4 d = *reinterpret_cast<const int4*>(&ei[e + i0]);
        int p0 = atomicAdd(&g_cur[d.x], 1);
        int p1 = atomicAdd(&g_cur[d.y], 1);
        int p2 = atomicAdd(&g_cur[d.z], 1);
        int p3 = atomicAdd(&g_cur[d.w], 1);
        g_adj[p0] = s.x; g_adj[p1] = s.y; g_adj[p2] = s.z; g_adj[p3] = s.w;
    } else {
        for (int i = i0; i < e; i++) {
            int pos = atomicAdd(&g_cur[ei[e + i]], 1);
            g_adj[pos] = ei[i];
        }
    }
}

// ---------------------------------------------------------------------------
// Per-node attention projections (b folded into alpha_dst)
// ---------------------------------------------------------------------------
__global__ void alpha_kernel(const float* __restrict__ Watt,
                             const float* __restrict__ batt, int n) {
    int idx = blockIdx.x * blockDim.x + threadIdx.x;
    if (idx >= n * NHEAD) return;
    int node = idx / NHEAD;
    int head = idx % NHEAD;
    const float* hp = &g_h[(size_t)node * DOUT + head * DH];
    float a = 0.f, b = batt[0];
    #pragma unroll
    for (int d = 0; d < DH; d++) {
        float v = hp[d];
        a += v * Watt[d];
        b += v * Watt[DH + d];
    }
    g_alpha_src[idx] = a;
    g_alpha_dst[idx] = b;
}

// ---------------------------------------------------------------------------
// Gather: warp per dst node, register softmax-weighted accumulation, no atomics
// ---------------------------------------------------------------------------
__global__ __launch_bounds__(256) void gather_kernel(float* __restrict__ out, int n) {
    int w = (blockIdx.x * blockDim.x + threadIdx.x) >> 5;
    if (w >= n) return;
    int lane = threadIdx.x & 31;
    int head = lane >> 2;

    int start = g_row[w];
    int deg   = g_cnt[w];
    float adst = g_alpha_dst[w * NHEAD + head];

    float s0 = g_alpha_src[w * NHEAD + head] + adst;
    s0 = (s0 >= 0.f) ? s0 : 0.2f * s0;
    float ev = __expf(s0);
    float denom = ev;
    float4 hv = *reinterpret_cast<const float4*>(&g_h[(size_t)w * DOUT + lane * 4]);
    float4 acc = make_float4(hv.x * ev, hv.y * ev, hv.z * ev, hv.w * ev);

    #pragma unroll 4
    for (int j = 0; j < deg; j++) {
        int src = __ldg(&g_adj[start + j]);
        float s = g_alpha_src[src * NHEAD + head] + adst;
        s = (s >= 0.f) ? s : 0.2f * s;
        float e2 = __expf(s);
        denom += e2;
        float4 v = *reinterpret_cast<const float4*>(&g_h[(size_t)src * DOUT + lane * 4]);
        acc.x += e2 * v.x;
        acc.y += e2 * v.y;
        acc.z += e2 * v.z;
        acc.w += e2 * v.w;
    }

    float inv = 1.f / denom;
    *reinterpret_cast<float4*>(&out[(size_t)w * DOUT + lane * 4]) =
        make_float4(acc.x * inv, acc.y * inv, acc.z * inv, acc.w * inv);
}

extern "C" void kernel_launch(void* const* d_in, const int* in_sizes, int n_in,
                              void* d_out, int out_size) {
    const float* x    = (const float*)d_in[0];
    const float* Wt   = (const float*)d_in[1];
    const float* Watt = (const float*)d_in[2];
    const float* batt = (const float*)d_in[3];
    const int*   ei   = (const int*)d_in[4];

    int n = in_sizes[0] / DIN;   // 50000
    int e = in_sizes[4] / 2;     // 800000
    float* out = (float*)d_out;

    // CSR build
    void* cntp = nullptr;
    cudaGetSymbolAddress(&cntp, g_cnt);
    cudaMemsetAsync(cntp, 0, (size_t)n * sizeof(int));
    int et = (e + 3) / 4;
    hist_kernel<<<(et + 255) / 256, 256>>>(ei, e);
    int nb = (n + 255) / 256;
    scan1_kernel<<<nb, 256>>>(n);
    scan2_kernel<<<1, 1024>>>(nb);
    scan3_kernel<<<nb, 256>>>(n);
    fill_kernel<<<(et + 255) / 256, 256>>>(ei, e);

    // h = x @ W^T (3xTF32 tensor core)
    gemm_tf32<<<(n + 127) / 128, 256>>>(x, Wt, n);
    int at = n * NHEAD;
    alpha_kernel<<<(at + 255) / 256, 256>>>(Watt, batt, n);

    // fused gather + softmax + normalize
    long long threads = (long long)n * 32;
    gather_kernel<<<(unsigned)((threads + 255) / 256), 256>>>(out, n);
}

// round 5
// speedup vs baseline: 1.4604x; 1.0104x over previous
#include <cuda_runtime.h>
#include <cstdint>

#define DIN  256
#define DOUT 128
#define NHEAD 8
#define DH   16

#define MAX_N 50000
#define MAX_E 800000

__device__ float g_h[MAX_N * DOUT];
__device__ float g_alpha_src[MAX_N * NHEAD];
__device__ float g_alpha_dst[MAX_N * NHEAD];
__device__ int   g_cnt[MAX_N];
__device__ int   g_row[MAX_N];
__device__ int   g_cur[MAX_N];
__device__ int   g_adj[MAX_E];
__device__ int   g_bsum[1024];

// ---------------------------------------------------------------------------
// tf32 helpers
// ---------------------------------------------------------------------------
__device__ __forceinline__ float tf32r(float x) {
    float y;
    asm("cvt.rna.tf32.f32 %0, %1;" : "=f"(y) : "f"(x));
    return y;
}

#define MMA_TF32(C, A, B)                                                     \
    asm volatile("mma.sync.aligned.m16n8k8.row.col.f32.tf32.tf32.f32 "        \
                 "{%0,%1,%2,%3}, {%4,%5,%6,%7}, {%8,%9}, {%0,%1,%2,%3};"      \
                 : "+f"((C)[0]), "+f"((C)[1]), "+f"((C)[2]), "+f"((C)[3])     \
                 : "r"((A)[0]), "r"((A)[1]), "r"((A)[2]), "r"((A)[3]),        \
                   "r"((B)[0]), "r"((B)[1]))

// ---------------------------------------------------------------------------
// 3xTF32 GEMM (NT): g_h[m,n] = sum_k A[m,k]*B[n,k]; A=[M,256], B=[128,256]
// Block: 128(M) x 128(N), K-tile 16, 256 threads = 8 warps (2M x 4N),
// warp tile 64x32 -> 4x4 m16n8k8 tiles. hi/lo split for fp32-class accuracy.
// ---------------------------------------------------------------------------
#define KT 16
#define SPAD 136
__global__ __launch_bounds__(256) void gemm_tf32(const float* __restrict__ A,
                                                 const float* __restrict__ B,
                                                 int M) {
    __shared__ float As_hi[KT][SPAD], As_lo[KT][SPAD];
    __shared__ float Bs_hi[KT][SPAD], Bs_lo[KT][SPAD];

    int tid = threadIdx.x;
    int blockRow = blockIdx.x * 128;
    int warpId = tid >> 5, lane = tid & 31;
    int g = lane >> 2, tig = lane & 3;
    int mBase = (warpId & 1) * 64;
    int nBase = (warpId >> 1) * 32;

    float c[4][4][4];
    #pragma unroll
    for (int mt = 0; mt < 4; mt++)
        #pragma unroll
        for (int nt = 0; nt < 4; nt++)
            #pragma unroll
            for (int r = 0; r < 4; r++) c[mt][nt][r] = 0.f;

    int lm = tid & 127;            // loader row (m for A, n for B)
    int lk = (tid >> 7) * 8;       // loader k offset within tile
    int gm = blockRow + lm;
    if (gm > M - 1) gm = M - 1;    // clamp (stores are guarded)

    for (int k0 = 0; k0 < DIN; k0 += KT) {
        #pragma unroll
        for (int q = 0; q < 2; q++) {
            float4 va = *reinterpret_cast<const float4*>(&A[(size_t)gm * DIN + k0 + lk + q * 4]);
            float4 vb = *reinterpret_cast<const float4*>(&B[(size_t)lm * DIN + k0 + lk + q * 4]);
            float av[4] = {va.x, va.y, va.z, va.w};
            float bv[4] = {vb.x, vb.y, vb.z, vb.w};
            #pragma unroll
            for (int j = 0; j < 4; j++) {
                int kk = lk + q * 4 + j;
                float ah = tf32r(av[j]);
                As_hi[kk][lm] = ah;
                As_lo[kk][lm] = tf32r(av[j] - ah);
                float bh = tf32r(bv[j]);
                Bs_hi[kk][lm] = bh;
                Bs_lo[kk][lm] = tf32r(bv[j] - bh);
            }
        }
        __syncthreads();

        #pragma unroll
        for (int kk = 0; kk < KT; kk += 8) {
            uint32_t a_hi[4][4], a_lo[4][4], b_hi[4][2], b_lo[4][2];
            #pragma unroll
            for (int mt = 0; mt < 4; mt++) {
                int m0 = mBase + mt * 16 + g;
                a_hi[mt][0] = __float_as_uint(As_hi[kk + tig][m0]);
                a_hi[mt][1] = __float_as_uint(As_hi[kk + tig][m0 + 8]);
                a_hi[mt][2] = __float_as_uint(As_hi[kk + tig + 4][m0]);
                a_hi[mt][3] = __float_as_uint(As_hi[kk + tig + 4][m0 + 8]);
                a_lo[mt][0] = __float_as_uint(As_lo[kk + tig][m0]);
                a_lo[mt][1] = __float_as_uint(As_lo[kk + tig][m0 + 8]);
                a_lo[mt][2] = __float_as_uint(As_lo[kk + tig + 4][m0]);
                a_lo[mt][3] = __float_as_uint(As_lo[kk + tig + 4][m0 + 8]);
            }
            #pragma unroll
            for (int nt = 0; nt < 4; nt++) {
                int n0 = nBase + nt * 8 + g;
                b_hi[nt][0] = __float_as_uint(Bs_hi[kk + tig][n0]);
                b_hi[nt][1] = __float_as_uint(Bs_hi[kk + tig + 4][n0]);
                b_lo[nt][0] = __float_as_uint(Bs_lo[kk + tig][n0]);
                b_lo[nt][1] = __float_as_uint(Bs_lo[kk + tig + 4][n0]);
            }
            #pragma unroll
            for (int mt = 0; mt < 4; mt++)
                #pragma unroll
                for (int nt = 0; nt < 4; nt++) {
                    MMA_TF32(c[mt][nt], a_hi[mt], b_hi[nt]);
                    MMA_TF32(c[mt][nt], a_lo[mt], b_hi[nt]);
                    MMA_TF32(c[mt][nt], a_hi[mt], b_lo[nt]);
                }
        }
        __syncthreads();
    }

    #pragma unroll
    for (int mt = 0; mt < 4; mt++) {
        int row0 = blockRow + mBase + mt * 16 + g;
        int row1 = row0 + 8;
        #pragma unroll
        for (int nt = 0; nt < 4; nt++) {
            int col = nBase + nt * 8 + tig * 2;
            if (row0 < M)
                *reinterpret_cast<float2*>(&g_h[(size_t)row0 * DOUT + col]) =
                    make_float2(c[mt][nt][0], c[mt][nt][1]);
            if (row1 < M)
                *reinterpret_cast<float2*>(&g_h[(size_t)row1 * DOUT + col]) =
                    make_float2(c[mt][nt][2], c[mt][nt][3]);
        }
    }
}

// ---------------------------------------------------------------------------
// CSR build
// ---------------------------------------------------------------------------
__global__ void hist_kernel(const int* __restrict__ ei, int e) {
    int i0 = (blockIdx.x * blockDim.x + threadIdx.x) * 4;
    if (i0 + 3 < e) {
        int4 d = *reinterpret_cast<const int4*>(&ei[e + i0]);
        atomicAdd(&g_cnt[d.x], 1);
        atomicAdd(&g_cnt[d.y], 1);
        atomicAdd(&g_cnt[d.z], 1);
        atomicAdd(&g_cnt[d.w], 1);
    } else {
        for (int i = i0; i < e; i++) atomicAdd(&g_cnt[ei[e + i]], 1);
    }
}

// pass 1: per-block sums of g_cnt
__global__ __launch_bounds__(256) void scan1_kernel(int n) {
    __shared__ int ws[8];
    int i = blockIdx.x * 256 + threadIdx.x;
    int v = (i < n) ? g_cnt[i] : 0;
    int lane = threadIdx.x & 31, wid = threadIdx.x >> 5;
    int s = v;
    #pragma unroll
    for (int o = 16; o > 0; o >>= 1) s += __shfl_down_sync(0xffffffffu, s, o);
    if (lane == 0) ws[wid] = s;
    __syncthreads();
    if (threadIdx.x == 0) {
        int t = 0;
        #pragma unroll
        for (int w = 0; w < 8; w++) t += ws[w];
        g_bsum[blockIdx.x] = t;
    }
}

// pass 2: exclusive scan of block sums (single block)
__global__ __launch_bounds__(1024) void scan2_kernel(int nb) {
    __shared__ int sh[1024];
    int t = threadIdx.x;
    int v = (t < nb) ? g_bsum[t] : 0;
    sh[t] = v;
    __syncthreads();
    for (int o = 1; o < 1024; o <<= 1) {
        int y = (t >= o) ? sh[t - o] : 0;
        __syncthreads();
        sh[t] += y;
        __syncthreads();
    }
    if (t < nb) g_bsum[t] = sh[t] - v;   // exclusive
}

// pass 3: local exclusive scan + block offset -> g_row, g_cur
__global__ __launch_bounds__(256) void scan3_kernel(int n) {
    __shared__ int ws[8];
    int i = blockIdx.x * 256 + threadIdx.x;
    int v = (i < n) ? g_cnt[i] : 0;
    int lane = threadIdx.x & 31, wid = threadIdx.x >> 5;
    int x = v;
    #pragma unroll
    for (int o = 1; o < 32; o <<= 1) {
        int y = __shfl_up_sync(0xffffffffu, x, o);
        if (lane >= o) x += y;
    }
    if (lane == 31) ws[wid] = x;
    __syncthreads();
    if (wid == 0 && lane < 8) {
        int s = ws[lane];
        #pragma unroll
        for (int o = 1; o < 8; o <<= 1) {
            int y = __shfl_up_sync(0xffu, s, o);
            if (lane >= o) s += y;
        }
        ws[lane] = s;
    }
    __syncthreads();
    int excl = x - v + ((wid > 0) ? ws[wid - 1] : 0) + g_bsum[blockIdx.x];
    if (i < n) { g_row[i] = excl; g_cur[i] = excl; }
}

__global__ void fill_kernel(const int* __restrict__ ei, int e) {
    int i0 = (blockIdx.x * blockDim.x + threadIdx.x) * 4;
    if (i0 + 3 < e) {
        int4 s = *reinterpret_cast<const int4*>(&ei[i0]);
        int4 d = *reinterpret_cast<const int4*>(&ei[e + i0]);
        int p0 = atomicAdd(&g_cur[d.x], 1);
        int p1 = atomicAdd(&g_cur[d.y], 1);
        int p2 = atomicAdd(&g_cur[d.z], 1);
        int p3 = atomicAdd(&g_cur[d.w], 1);
        g_adj[p0] = s.x; g_adj[p1] = s.y; g_adj[p2] = s.z; g_adj[p3] = s.w;
    } else {
        for (int i = i0; i < e; i++) {
            int pos = atomicAdd(&g_cur[ei[e + i]], 1);
            g_adj[pos] = ei[i];
        }
    }
}

// ---------------------------------------------------------------------------
// Per-node attention projections (b folded into alpha_dst)
// ---------------------------------------------------------------------------
__global__ void alpha_kernel(const float* __restrict__ Watt,
                             const float* __restrict__ batt, int n) {
    int idx = blockIdx.x * blockDim.x + threadIdx.x;
    if (idx >= n * NHEAD) return;
    int node = idx / NHEAD;
    int head = idx % NHEAD;
    const float* hp = &g_h[(size_t)node * DOUT + head * DH];
    float a = 0.f, b = batt[0];
    #pragma unroll
    for (int d = 0; d < DH; d++) {
        float v = hp[d];
        a += v * Watt[d];
        b += v * Watt[DH + d];
    }
    g_alpha_src[idx] = a;
    g_alpha_dst[idx] = b;
}

// ---------------------------------------------------------------------------
// Gather: warp per dst node, register softmax-weighted accumulation, no atomics
// ---------------------------------------------------------------------------
__global__ __launch_bounds__(256) void gather_kernel(float* __restrict__ out, int n) {
    int w = (blockIdx.x * blockDim.x + threadIdx.x) >> 5;
    if (w >= n) return;
    int lane = threadIdx.x & 31;
    int head = lane >> 2;

    int start = g_row[w];
    int deg   = g_cnt[w];
    float adst = g_alpha_dst[w * NHEAD + head];

    float s0 = g_alpha_src[w * NHEAD + head] + adst;
    s0 = (s0 >= 0.f) ? s0 : 0.2f * s0;
    float ev = __expf(s0);
    float denom = ev;
    float4 hv = *reinterpret_cast<const float4*>(&g_h[(size_t)w * DOUT + lane * 4]);
    float4 acc = make_float4(hv.x * ev, hv.y * ev, hv.z * ev, hv.w * ev);

    #pragma unroll 4
    for (int j = 0; j < deg; j++) {
        int src = __ldg(&g_adj[start + j]);
        float s = g_alpha_src[src * NHEAD + head] + adst;
        s = (s >= 0.f) ? s : 0.2f * s;
        float e2 = __expf(s);
        denom += e2;
        float4 v = *reinterpret_cast<const float4*>(&g_h[(size_t)src * DOUT + lane * 4]);
        acc.x += e2 * v.x;
        acc.y += e2 * v.y;
        acc.z += e2 * v.z;
        acc.w += e2 * v.w;
    }

    float inv = 1.f / denom;
    *reinterpret_cast<float4*>(&out[(size_t)w * DOUT + lane * 4]) =
        make_float4(acc.x * inv, acc.y * inv, acc.z * inv, acc.w * inv);
}

extern "C" void kernel_launch(void* const* d_in, const int* in_sizes, int n_in,
                              void* d_out, int out_size) {
    const float* x    = (const float*)d_in[0];
    const float* Wt   = (const float*)d_in[1];
    const float* Watt = (const float*)d_in[2];
    const float* batt = (const float*)d_in[3];
    const int*   ei   = (const int*)d_in[4];

    int n = in_sizes[0] / DIN;   // 50000
    int e = in_sizes[4] / 2;     // 800000
    float* out = (float*)d_out;

    // CSR build
    void* cntp = nullptr;
    cudaGetSymbolAddress(&cntp, g_cnt);
    cudaMemsetAsync(cntp, 0, (size_t)n * sizeof(int));
    int et = (e + 3) / 4;
    hist_kernel<<<(et + 255) / 256, 256>>>(ei, e);
    int nb = (n + 255) / 256;
    scan1_kernel<<<nb, 256>>>(n);
    scan2_kernel<<<1, 1024>>>(nb);
    scan3_kernel<<<nb, 256>>>(n);
    fill_kernel<<<(et + 255) / 256, 256>>>(ei, e);

    // h = x @ W^T (3xTF32 tensor core)
    gemm_tf32<<<(n + 127) / 128, 256>>>(x, Wt, n);
    int at = n * NHEAD;
    alpha_kernel<<<(at + 255) / 256, 256>>>(Watt, batt, n);

    // fused gather + softmax + normalize
    long long threads = (long long)n * 32;
    gather_kernel<<<(unsigned)((threads + 255) / 256), 256>>>(out, n);
}

// round 6
// speedup vs baseline: 1.7085x; 1.1699x over previous
#include <cuda_runtime.h>
#include <cstdint>

#define DIN  256
#define DOUT 128
#define NHEAD 8
#define DH   16

#define MAX_N 50000
#define MAX_E 800000

__device__ float g_h[MAX_N * DOUT];
__device__ float g_alpha_src[MAX_N * NHEAD];
__device__ float g_alpha_dst[MAX_N * NHEAD];
__device__ int   g_cnt[MAX_N];
__device__ int   g_row[MAX_N];
__device__ int   g_adj[MAX_E];
__device__ int   g_pos[MAX_E];
__device__ int   g_bsum[1024];

// ---------------------------------------------------------------------------
// tf32 helpers
// ---------------------------------------------------------------------------
__device__ __forceinline__ float tf32r(float x) {
    float y;
    asm("cvt.rna.tf32.f32 %0, %1;" : "=f"(y) : "f"(x));
    return y;
}

#define MMA_TF32(C, A, B)                                                     \
    asm volatile("mma.sync.aligned.m16n8k8.row.col.f32.tf32.tf32.f32 "        \
                 "{%0,%1,%2,%3}, {%4,%5,%6,%7}, {%8,%9}, {%0,%1,%2,%3};"      \
                 : "+f"((C)[0]), "+f"((C)[1]), "+f"((C)[2]), "+f"((C)[3])     \
                 : "r"((A)[0]), "r"((A)[1]), "r"((A)[2]), "r"((A)[3]),        \
                   "r"((B)[0]), "r"((B)[1]))

// ---------------------------------------------------------------------------
// 3xTF32 GEMM (NT) with register double-buffer prefetch of global loads.
// ---------------------------------------------------------------------------
#define KT 16
#define SPAD 136
__global__ __launch_bounds__(256) void gemm_tf32(const float* __restrict__ A,
                                                 const float* __restrict__ B,
                                                 int M) {
    __shared__ float As_hi[KT][SPAD], As_lo[KT][SPAD];
    __shared__ float Bs_hi[KT][SPAD], Bs_lo[KT][SPAD];

    int tid = threadIdx.x;
    int blockRow = blockIdx.x * 128;
    int warpId = tid >> 5, lane = tid & 31;
    int g = lane >> 2, tig = lane & 3;
    int mBase = (warpId & 1) * 64;
    int nBase = (warpId >> 1) * 32;

    float c[4][4][4];
    #pragma unroll
    for (int mt = 0; mt < 4; mt++)
        #pragma unroll
        for (int nt = 0; nt < 4; nt++)
            #pragma unroll
            for (int r = 0; r < 4; r++) c[mt][nt][r] = 0.f;

    int lm = tid & 127;
    int lk = (tid >> 7) * 8;
    int gm = blockRow + lm;
    if (gm > M - 1) gm = M - 1;

    float4 pva0, pva1, pvb0, pvb1;

    // prologue: load tile 0
    pva0 = *reinterpret_cast<const float4*>(&A[(size_t)gm * DIN + lk]);
    pva1 = *reinterpret_cast<const float4*>(&A[(size_t)gm * DIN + lk + 4]);
    pvb0 = *reinterpret_cast<const float4*>(&B[(size_t)lm * DIN + lk]);
    pvb1 = *reinterpret_cast<const float4*>(&B[(size_t)lm * DIN + lk + 4]);

    for (int t = 0; t < DIN / KT; t++) {
        // store prefetched tile to smem (with hi/lo split)
        {
            float av[8] = {pva0.x, pva0.y, pva0.z, pva0.w, pva1.x, pva1.y, pva1.z, pva1.w};
            float bv[8] = {pvb0.x, pvb0.y, pvb0.z, pvb0.w, pvb1.x, pvb1.y, pvb1.z, pvb1.w};
            #pragma unroll
            for (int j = 0; j < 8; j++) {
                int kk = lk + j;
                float ah = tf32r(av[j]);
                As_hi[kk][lm] = ah;
                As_lo[kk][lm] = tf32r(av[j] - ah);
                float bh = tf32r(bv[j]);
                Bs_hi[kk][lm] = bh;
                Bs_lo[kk][lm] = tf32r(bv[j] - bh);
            }
        }
        __syncthreads();

        // prefetch next tile's globals into registers
        if (t + 1 < DIN / KT) {
            int k0 = (t + 1) * KT;
            pva0 = *reinterpret_cast<const float4*>(&A[(size_t)gm * DIN + k0 + lk]);
            pva1 = *reinterpret_cast<const float4*>(&A[(size_t)gm * DIN + k0 + lk + 4]);
            pvb0 = *reinterpret_cast<const float4*>(&B[(size_t)lm * DIN + k0 + lk]);
            pvb1 = *reinterpret_cast<const float4*>(&B[(size_t)lm * DIN + k0 + lk + 4]);
        }

        #pragma unroll
        for (int kk = 0; kk < KT; kk += 8) {
            uint32_t a_hi[4][4], a_lo[4][4], b_hi[4][2], b_lo[4][2];
            #pragma unroll
            for (int mt = 0; mt < 4; mt++) {
                int m0 = mBase + mt * 16 + g;
                a_hi[mt][0] = __float_as_uint(As_hi[kk + tig][m0]);
                a_hi[mt][1] = __float_as_uint(As_hi[kk + tig][m0 + 8]);
                a_hi[mt][2] = __float_as_uint(As_hi[kk + tig + 4][m0]);
                a_hi[mt][3] = __float_as_uint(As_hi[kk + tig + 4][m0 + 8]);
                a_lo[mt][0] = __float_as_uint(As_lo[kk + tig][m0]);
                a_lo[mt][1] = __float_as_uint(As_lo[kk + tig][m0 + 8]);
                a_lo[mt][2] = __float_as_uint(As_lo[kk + tig + 4][m0]);
                a_lo[mt][3] = __float_as_uint(As_lo[kk + tig + 4][m0 + 8]);
            }
            #pragma unroll
            for (int nt = 0; nt < 4; nt++) {
                int n0 = nBase + nt * 8 + g;
                b_hi[nt][0] = __float_as_uint(Bs_hi[kk + tig][n0]);
                b_hi[nt][1] = __float_as_uint(Bs_hi[kk + tig + 4][n0]);
                b_lo[nt][0] = __float_as_uint(Bs_lo[kk + tig][n0]);
                b_lo[nt][1] = __float_as_uint(Bs_lo[kk + tig + 4][n0]);
            }
            #pragma unroll
            for (int mt = 0; mt < 4; mt++)
                #pragma unroll
                for (int nt = 0; nt < 4; nt++) {
                    MMA_TF32(c[mt][nt], a_hi[mt], b_hi[nt]);
                    MMA_TF32(c[mt][nt], a_lo[mt], b_hi[nt]);
                    MMA_TF32(c[mt][nt], a_hi[mt], b_lo[nt]);
                }
        }
        __syncthreads();
    }

    #pragma unroll
    for (int mt = 0; mt < 4; mt++) {
        int row0 = blockRow + mBase + mt * 16 + g;
        int row1 = row0 + 8;
        #pragma unroll
        for (int nt = 0; nt < 4; nt++) {
            int col = nBase + nt * 8 + tig * 2;
            if (row0 < M)
                *reinterpret_cast<float2*>(&g_h[(size_t)row0 * DOUT + col]) =
                    make_float2(c[mt][nt][0], c[mt][nt][1]);
            if (row1 < M)
                *reinterpret_cast<float2*>(&g_h[(size_t)row1 * DOUT + col]) =
                    make_float2(c[mt][nt][2], c[mt][nt][3]);
        }
    }
}

// ---------------------------------------------------------------------------
// CSR build. hist also records each edge's rank within its dst bucket so the
// fill pass needs no atomics.
// ---------------------------------------------------------------------------
__global__ void hist_kernel(const int* __restrict__ ei, int e) {
    int i0 = (blockIdx.x * blockDim.x + threadIdx.x) * 4;
    if (((e & 3) == 0) && i0 + 3 < e) {
        int4 d = *reinterpret_cast<const int4*>(&ei[e + i0]);
        int4 p;
        p.x = atomicAdd(&g_cnt[d.x], 1);
        p.y = atomicAdd(&g_cnt[d.y], 1);
        p.z = atomicAdd(&g_cnt[d.z], 1);
        p.w = atomicAdd(&g_cnt[d.w], 1);
        *reinterpret_cast<int4*>(&g_pos[i0]) = p;
    } else {
        for (int i = i0; i < e && i < i0 + 4; i++)
            g_pos[i] = atomicAdd(&g_cnt[ei[e + i]], 1);
    }
}

__global__ __launch_bounds__(256) void scan1_kernel(int n) {
    __shared__ int ws[8];
    int i = blockIdx.x * 256 + threadIdx.x;
    int v = (i < n) ? g_cnt[i] : 0;
    int lane = threadIdx.x & 31, wid = threadIdx.x >> 5;
    int s = v;
    #pragma unroll
    for (int o = 16; o > 0; o >>= 1) s += __shfl_down_sync(0xffffffffu, s, o);
    if (lane == 0) ws[wid] = s;
    __syncthreads();
    if (threadIdx.x == 0) {
        int t = 0;
        #pragma unroll
        for (int w = 0; w < 8; w++) t += ws[w];
        g_bsum[blockIdx.x] = t;
    }
}

__global__ __launch_bounds__(1024) void scan2_kernel(int nb) {
    __shared__ int sh[1024];
    int t = threadIdx.x;
    int v = (t < nb) ? g_bsum[t] : 0;
    sh[t] = v;
    __syncthreads();
    for (int o = 1; o < 1024; o <<= 1) {
        int y = (t >= o) ? sh[t - o] : 0;
        __syncthreads();
        sh[t] += y;
        __syncthreads();
    }
    if (t < nb) g_bsum[t] = sh[t] - v;
}

__global__ __launch_bounds__(256) void scan3_kernel(int n) {
    __shared__ int ws[8];
    int i = blockIdx.x * 256 + threadIdx.x;
    int v = (i < n) ? g_cnt[i] : 0;
    int lane = threadIdx.x & 31, wid = threadIdx.x >> 5;
    int x = v;
    #pragma unroll
    for (int o = 1; o < 32; o <<= 1) {
        int y = __shfl_up_sync(0xffffffffu, x, o);
        if (lane >= o) x += y;
    }
    if (lane == 31) ws[wid] = x;
    __syncthreads();
    if (wid == 0 && lane < 8) {
        int s = ws[lane];
        #pragma unroll
        for (int o = 1; o < 8; o <<= 1) {
            int y = __shfl_up_sync(0xffu, s, o);
            if (lane >= o) s += y;
        }
        ws[lane] = s;
    }
    __syncthreads();
    int excl = x - v + ((wid > 0) ? ws[wid - 1] : 0) + g_bsum[blockIdx.x];
    if (i < n) g_row[i] = excl;
}

// Atomic-free scatter using precomputed ranks.
__global__ void fill_kernel(const int* __restrict__ ei, int e) {
    int i0 = (blockIdx.x * blockDim.x + threadIdx.x) * 4;
    if (((e & 3) == 0) && i0 + 3 < e) {
        int4 s = *reinterpret_cast<const int4*>(&ei[i0]);
        int4 d = *reinterpret_cast<const int4*>(&ei[e + i0]);
        int4 p = *reinterpret_cast<const int4*>(&g_pos[i0]);
        g_adj[g_row[d.x] + p.x] = s.x;
        g_adj[g_row[d.y] + p.y] = s.y;
        g_adj[g_row[d.z] + p.z] = s.z;
        g_adj[g_row[d.w] + p.w] = s.w;
    } else {
        for (int i = i0; i < e && i < i0 + 4; i++)
            g_adj[g_row[ei[e + i]] + g_pos[i]] = ei[i];
    }
}

// ---------------------------------------------------------------------------
// Per-node attention projections (b folded into alpha_dst)
// ---------------------------------------------------------------------------
__global__ void alpha_kernel(const float* __restrict__ Watt,
                             const float* __restrict__ batt, int n) {
    int idx = blockIdx.x * blockDim.x + threadIdx.x;
    if (idx >= n * NHEAD) return;
    int node = idx / NHEAD;
    int head = idx % NHEAD;
    const float* hp = &g_h[(size_t)node * DOUT + head * DH];
    float a = 0.f, b = batt[0];
    #pragma unroll
    for (int d = 0; d < DH; d++) {
        float v = hp[d];
        a += v * Watt[d];
        b += v * Watt[DH + d];
    }
    g_alpha_src[idx] = a;
    g_alpha_dst[idx] = b;
}

// ---------------------------------------------------------------------------
// Gather: warp per dst node, register softmax accumulation, no atomics
// ---------------------------------------------------------------------------
__global__ __launch_bounds__(256) void gather_kernel(float* __restrict__ out, int n) {
    int w = (blockIdx.x * blockDim.x + threadIdx.x) >> 5;
    if (w >= n) return;
    int lane = threadIdx.x & 31;
    int head = lane >> 2;

    int start = g_row[w];
    int deg   = g_cnt[w];
    float adst = g_alpha_dst[w * NHEAD + head];

    float s0 = g_alpha_src[w * NHEAD + head] + adst;
    s0 = (s0 >= 0.f) ? s0 : 0.2f * s0;
    float ev = __expf(s0);
    float denom = ev;
    float4 hv = *reinterpret_cast<const float4*>(&g_h[(size_t)w * DOUT + lane * 4]);
    float4 acc = make_float4(hv.x * ev, hv.y * ev, hv.z * ev, hv.w * ev);

    #pragma unroll 4
    for (int j = 0; j < deg; j++) {
        int src = __ldg(&g_adj[start + j]);
        float s = g_alpha_src[src * NHEAD + head] + adst;
        s = (s >= 0.f) ? s : 0.2f * s;
        float e2 = __expf(s);
        denom += e2;
        float4 v = *reinterpret_cast<const float4*>(&g_h[(size_t)src * DOUT + lane * 4]);
        acc.x += e2 * v.x;
        acc.y += e2 * v.y;
        acc.z += e2 * v.z;
        acc.w += e2 * v.w;
    }

    float inv = 1.f / denom;
    *reinterpret_cast<float4*>(&out[(size_t)w * DOUT + lane * 4]) =
        make_float4(acc.x * inv, acc.y * inv, acc.z * inv, acc.w * inv);
}

extern "C" void kernel_launch(void* const* d_in, const int* in_sizes, int n_in,
                              void* d_out, int out_size) {
    const float* x    = (const float*)d_in[0];
    const float* Wt   = (const float*)d_in[1];
    const float* Watt = (const float*)d_in[2];
    const float* batt = (const float*)d_in[3];
    const int*   ei   = (const int*)d_in[4];

    int n = in_sizes[0] / DIN;   // 50000
    int e = in_sizes[4] / 2;     // 800000
    float* out = (float*)d_out;

    // One-time handle creation (happens on the uncaptured correctness call;
    // enqueued GPU work is identical on every call).
    static cudaStream_t s2 = nullptr;
    static cudaEvent_t evF = nullptr, evJ = nullptr;
    if (s2 == nullptr) {
        cudaStreamCreateWithFlags(&s2, cudaStreamNonBlocking);
        cudaEventCreateWithFlags(&evF, cudaEventDisableTiming);
        cudaEventCreateWithFlags(&evJ, cudaEventDisableTiming);
    }

    void* cntp = nullptr;
    cudaGetSymbolAddress(&cntp, g_cnt);

    // fork: CSR build on s2, concurrent with GEMM chain on the main stream
    cudaEventRecord(evF, 0);
    cudaStreamWaitEvent(s2, evF, 0);

    cudaMemsetAsync(cntp, 0, (size_t)n * sizeof(int), s2);
    int et = (e + 3) / 4;
    hist_kernel<<<(et + 255) / 256, 256, 0, s2>>>(ei, e);
    int nb = (n + 255) / 256;
    scan1_kernel<<<nb, 256, 0, s2>>>(n);
    scan2_kernel<<<1, 1024, 0, s2>>>(nb);
    scan3_kernel<<<nb, 256, 0, s2>>>(n);
    fill_kernel<<<(et + 255) / 256, 256, 0, s2>>>(ei, e);
    cudaEventRecord(evJ, s2);

    // main stream: feature transform + attention projections
    gemm_tf32<<<(n + 127) / 128, 256>>>(x, Wt, n);
    int at = n * NHEAD;
    alpha_kernel<<<(at + 255) / 256, 256>>>(Watt, batt, n);

    // join, then fused gather + softmax + normalize
    cudaStreamWaitEvent(0, evJ, 0);
    long long threads = (long long)n * 32;
    gather_kernel<<<(unsigned)((threads + 255) / 256), 256>>>(out, n);
}

// round 7
// speedup vs baseline: 2.5568x; 1.4965x over previous
#include <cuda_runtime.h>
#include <cuda_fp16.h>
#include <cstdint>

#define DIN  256
#define DOUT 128
#define NHEAD 8
#define DH   16

#define MAX_N 50000
#define MAX_E 800000

__device__ __half g_h16[MAX_N * DOUT];
__device__ float g_alpha_src[MAX_N * NHEAD];
__device__ float g_alpha_dst[MAX_N * NHEAD];
__device__ int   g_cnt[MAX_N];
__device__ int   g_row[MAX_N];
__device__ int   g_adj[MAX_E];
__device__ int   g_pos[MAX_E];
__device__ int   g_bsum[1024];

#define MMA_F16(C, A, B)                                                      \
    asm volatile("mma.sync.aligned.m16n8k16.row.col.f32.f16.f16.f32 "         \
                 "{%0,%1,%2,%3}, {%4,%5,%6,%7}, {%8,%9}, {%0,%1,%2,%3};"      \
                 : "+f"((C)[0]), "+f"((C)[1]), "+f"((C)[2]), "+f"((C)[3])     \
                 : "r"((A)[0]), "r"((A)[1]), "r"((A)[2]), "r"((A)[3]),        \
                   "r"((B)[0]), "r"((B)[1]))

// ---------------------------------------------------------------------------
// fp16 GEMM (NT), fp32 accumulate: g_h16[m,n] = sum_k A[m,k]*B[n,k]
// A=[M,256] f32, B=[128,256] f32 (converted to f16 in the smem loader).
// Block 128(M) x 128(N), K-tile 32, 256 threads = 8 warps (2M x 4N),
// warp tile 64x32 -> 4x4 m16n8k16 tiles, 2 k-steps per tile.
// ---------------------------------------------------------------------------
#define KT 32
#define ROWP 40   // smem row pitch in halves (80B): conflict-free frag reads
__global__ __launch_bounds__(256) void gemm_f16(const float* __restrict__ A,
                                                const float* __restrict__ B,
                                                int M) {
    __shared__ __half As[128][ROWP];
    __shared__ __half Bs[128][ROWP];

    int tid = threadIdx.x;
    int blockRow = blockIdx.x * 128;
    int warpId = tid >> 5, lane = tid & 31;
    int g = lane >> 2, tig = lane & 3;
    int mBase = (warpId & 1) * 64;
    int nBase = (warpId >> 1) * 32;

    float c[4][4][4];
    #pragma unroll
    for (int mt = 0; mt < 4; mt++)
        #pragma unroll
        for (int nt = 0; nt < 4; nt++)
            #pragma unroll
            for (int r = 0; r < 4; r++) c[mt][nt][r] = 0.f;

    int lm = tid & 127;
    int lk = (tid >> 7) * 16;    // 0 or 16
    int gm = blockRow + lm;
    if (gm > M - 1) gm = M - 1;  // clamp; stores guarded

    float4 pa[4], pb[4];
    #pragma unroll
    for (int q = 0; q < 4; q++) {
        pa[q] = *reinterpret_cast<const float4*>(&A[(size_t)gm * DIN + lk + q * 4]);
        pb[q] = *reinterpret_cast<const float4*>(&B[(size_t)lm * DIN + lk + q * 4]);
    }

    for (int t = 0; t < DIN / KT; t++) {
        // convert + store prefetched tile
        #pragma unroll
        for (int q = 0; q < 4; q++) {
            __half2* ap = reinterpret_cast<__half2*>(&As[lm][lk + q * 4]);
            __half2* bp = reinterpret_cast<__half2*>(&Bs[lm][lk + q * 4]);
            ap[0] = __floats2half2_rn(pa[q].x, pa[q].y);
            ap[1] = __floats2half2_rn(pa[q].z, pa[q].w);
            bp[0] = __floats2half2_rn(pb[q].x, pb[q].y);
            bp[1] = __floats2half2_rn(pb[q].z, pb[q].w);
        }
        __syncthreads();

        if (t + 1 < DIN / KT) {
            int k0 = (t + 1) * KT;
            #pragma unroll
            for (int q = 0; q < 4; q++) {
                pa[q] = *reinterpret_cast<const float4*>(&A[(size_t)gm * DIN + k0 + lk + q * 4]);
                pb[q] = *reinterpret_cast<const float4*>(&B[(size_t)lm * DIN + k0 + lk + q * 4]);
            }
        }

        #pragma unroll
        for (int kk = 0; kk < KT; kk += 16) {
            int kh = (kk >> 1) + tig;  // half2 index for k = kk + tig*2
            uint32_t a_fr[4][4], b_fr[4][2];
            #pragma unroll
            for (int mt = 0; mt < 4; mt++) {
                int m0 = mBase + mt * 16 + g;
                const __half2* r0 = reinterpret_cast<const __half2*>(&As[m0][0]);
                const __half2* r1 = reinterpret_cast<const __half2*>(&As[m0 + 8][0]);
                a_fr[mt][0] = *reinterpret_cast<const uint32_t*>(&r0[kh]);
                a_fr[mt][1] = *reinterpret_cast<const uint32_t*>(&r1[kh]);
                a_fr[mt][2] = *reinterpret_cast<const uint32_t*>(&r0[kh + 4]);
                a_fr[mt][3] = *reinterpret_cast<const uint32_t*>(&r1[kh + 4]);
            }
            #pragma unroll
            for (int nt = 0; nt < 4; nt++) {
                int n0 = nBase + nt * 8 + g;
                const __half2* rb = reinterpret_cast<const __half2*>(&Bs[n0][0]);
                b_fr[nt][0] = *reinterpret_cast<const uint32_t*>(&rb[kh]);
                b_fr[nt][1] = *reinterpret_cast<const uint32_t*>(&rb[kh + 4]);
            }
            #pragma unroll
            for (int mt = 0; mt < 4; mt++)
                #pragma unroll
                for (int nt = 0; nt < 4; nt++)
                    MMA_F16(c[mt][nt], a_fr[mt], b_fr[nt]);
        }
        __syncthreads();
    }

    #pragma unroll
    for (int mt = 0; mt < 4; mt++) {
        int row0 = blockRow + mBase + mt * 16 + g;
        int row1 = row0 + 8;
        #pragma unroll
        for (int nt = 0; nt < 4; nt++) {
            int col = nBase + nt * 8 + tig * 2;
            if (row0 < M)
                *reinterpret_cast<__half2*>(&g_h16[(size_t)row0 * DOUT + col]) =
                    __floats2half2_rn(c[mt][nt][0], c[mt][nt][1]);
            if (row1 < M)
                *reinterpret_cast<__half2*>(&g_h16[(size_t)row1 * DOUT + col]) =
                    __floats2half2_rn(c[mt][nt][2], c[mt][nt][3]);
        }
    }
}

// ---------------------------------------------------------------------------
// CSR build (hist records within-bucket rank -> atomic-free fill)
// ---------------------------------------------------------------------------
__global__ void hist_kernel(const int* __restrict__ ei, int e) {
    int i0 = (blockIdx.x * blockDim.x + threadIdx.x) * 4;
    if (((e & 3) == 0) && i0 + 3 < e) {
        int4 d = *reinterpret_cast<const int4*>(&ei[e + i0]);
        int4 p;
        p.x = atomicAdd(&g_cnt[d.x], 1);
        p.y = atomicAdd(&g_cnt[d.y], 1);
        p.z = atomicAdd(&g_cnt[d.z], 1);
        p.w = atomicAdd(&g_cnt[d.w], 1);
        *reinterpret_cast<int4*>(&g_pos[i0]) = p;
    } else {
        for (int i = i0; i < e && i < i0 + 4; i++)
            g_pos[i] = atomicAdd(&g_cnt[ei[e + i]], 1);
    }
}

__global__ __launch_bounds__(256) void scan1_kernel(int n) {
    __shared__ int ws[8];
    int i = blockIdx.x * 256 + threadIdx.x;
    int v = (i < n) ? g_cnt[i] : 0;
    int lane = threadIdx.x & 31, wid = threadIdx.x >> 5;
    int s = v;
    #pragma unroll
    for (int o = 16; o > 0; o >>= 1) s += __shfl_down_sync(0xffffffffu, s, o);
    if (lane == 0) ws[wid] = s;
    __syncthreads();
    if (threadIdx.x == 0) {
        int t = 0;
        #pragma unroll
        for (int w = 0; w < 8; w++) t += ws[w];
        g_bsum[blockIdx.x] = t;
    }
}

__global__ __launch_bounds__(1024) void scan2_kernel(int nb) {
    __shared__ int sh[1024];
    int t = threadIdx.x;
    int v = (t < nb) ? g_bsum[t] : 0;
    sh[t] = v;
    __syncthreads();
    for (int o = 1; o < 1024; o <<= 1) {
        int y = (t >= o) ? sh[t - o] : 0;
        __syncthreads();
        sh[t] += y;
        __syncthreads();
    }
    if (t < nb) g_bsum[t] = sh[t] - v;
}

__global__ __launch_bounds__(256) void scan3_kernel(int n) {
    __shared__ int ws[8];
    int i = blockIdx.x * 256 + threadIdx.x;
    int v = (i < n) ? g_cnt[i] : 0;
    int lane = threadIdx.x & 31, wid = threadIdx.x >> 5;
    int x = v;
    #pragma unroll
    for (int o = 1; o < 32; o <<= 1) {
        int y = __shfl_up_sync(0xffffffffu, x, o);
        if (lane >= o) x += y;
    }
    if (lane == 31) ws[wid] = x;
    __syncthreads();
    if (wid == 0 && lane < 8) {
        int s = ws[lane];
        #pragma unroll
        for (int o = 1; o < 8; o <<= 1) {
            int y = __shfl_up_sync(0xffu, s, o);
            if (lane >= o) s += y;
        }
        ws[lane] = s;
    }
    __syncthreads();
    int excl = x - v + ((wid > 0) ? ws[wid - 1] : 0) + g_bsum[blockIdx.x];
    if (i < n) g_row[i] = excl;
}

__global__ void fill_kernel(const int* __restrict__ ei, int e) {
    int i0 = (blockIdx.x * blockDim.x + threadIdx.x) * 4;
    if (((e & 3) == 0) && i0 + 3 < e) {
        int4 s = *reinterpret_cast<const int4*>(&ei[i0]);
        int4 d = *reinterpret_cast<const int4*>(&ei[e + i0]);
        int4 p = *reinterpret_cast<const int4*>(&g_pos[i0]);
        g_adj[g_row[d.x] + p.x] = s.x;
        g_adj[g_row[d.y] + p.y] = s.y;
        g_adj[g_row[d.z] + p.z] = s.z;
        g_adj[g_row[d.w] + p.w] = s.w;
    } else {
        for (int i = i0; i < e && i < i0 + 4; i++)
            g_adj[g_row[ei[e + i]] + g_pos[i]] = ei[i];
    }
}

// ---------------------------------------------------------------------------
// Per-node attention projections from fp16 h (fp32 math, b folded into dst)
// ---------------------------------------------------------------------------
__global__ void alpha_kernel(const float* __restrict__ Watt,
                             const float* __restrict__ batt, int n) {
    int idx = blockIdx.x * blockDim.x + threadIdx.x;
    if (idx >= n * NHEAD) return;
    int node = idx / NHEAD;
    int head = idx % NHEAD;
    const __half2* hp = reinterpret_cast<const __half2*>(
        &g_h16[(size_t)node * DOUT + head * DH]);
    float a = 0.f, b = batt[0];
    #pragma unroll
    for (int d = 0; d < DH / 2; d++) {
        float2 v = __half22float2(hp[d]);
        a += v.x * Watt[2 * d]     + v.y * Watt[2 * d + 1];
        b += v.x * Watt[DH + 2 * d] + v.y * Watt[DH + 2 * d + 1];
    }
    g_alpha_src[idx] = a;
    g_alpha_dst[idx] = b;
}

// ---------------------------------------------------------------------------
// Gather: warp per dst node; fp16 h rows (8B/lane), fp32 accumulation
// ---------------------------------------------------------------------------
__global__ __launch_bounds__(256) void gather_kernel(float* __restrict__ out, int n) {
    int w = (blockIdx.x * blockDim.x + threadIdx.x) >> 5;
    if (w >= n) return;
    int lane = threadIdx.x & 31;
    int head = lane >> 2;

    int start = g_row[w];
    int deg   = g_cnt[w];
    float adst = g_alpha_dst[w * NHEAD + head];

    float s0 = g_alpha_src[w * NHEAD + head] + adst;
    s0 = (s0 >= 0.f) ? s0 : 0.2f * s0;
    float ev = __expf(s0);
    float denom = ev;

    const __half2* hp = reinterpret_cast<const __half2*>(
        &g_h16[(size_t)w * DOUT + lane * 4]);
    float2 f0 = __half22float2(hp[0]);
    float2 f1 = __half22float2(hp[1]);
    float4 acc = make_float4(f0.x * ev, f0.y * ev, f1.x * ev, f1.y * ev);

    #pragma unroll 4
    for (int j = 0; j < deg; j++) {
        int src = __ldg(&g_adj[start + j]);
        float s = g_alpha_src[src * NHEAD + head] + adst;
        s = (s >= 0.f) ? s : 0.2f * s;
        float e2 = __expf(s);
        denom += e2;
        const __half2* vp = reinterpret_cast<const __half2*>(
            &g_h16[(size_t)src * DOUT + lane * 4]);
        float2 v0 = __half22float2(vp[0]);
        float2 v1 = __half22float2(vp[1]);
        acc.x += e2 * v0.x;
        acc.y += e2 * v0.y;
        acc.z += e2 * v1.x;
        acc.w += e2 * v1.y;
    }

    float inv = 1.f / denom;
    *reinterpret_cast<float4*>(&out[(size_t)w * DOUT + lane * 4]) =
        make_float4(acc.x * inv, acc.y * inv, acc.z * inv, acc.w * inv);
}

extern "C" void kernel_launch(void* const* d_in, const int* in_sizes, int n_in,
                              void* d_out, int out_size) {
    const float* x    = (const float*)d_in[0];
    const float* Wt   = (const float*)d_in[1];
    const float* Watt = (const float*)d_in[2];
    const float* batt = (const float*)d_in[3];
    const int*   ei   = (const int*)d_in[4];

    int n = in_sizes[0] / DIN;   // 50000
    int e = in_sizes[4] / 2;     // 800000
    float* out = (float*)d_out;

    static cudaStream_t s2 = nullptr;
    static cudaEvent_t evF = nullptr, evJ = nullptr;
    if (s2 == nullptr) {
        cudaStreamCreateWithFlags(&s2, cudaStreamNonBlocking);
        cudaEventCreateWithFlags(&evF, cudaEventDisableTiming);
        cudaEventCreateWithFlags(&evJ, cudaEventDisableTiming);
    }

    void* cntp = nullptr;
    cudaGetSymbolAddress(&cntp, g_cnt);

    // fork: CSR build on s2, concurrent with GEMM chain on main stream
    cudaEventRecord(evF, 0);
    cudaStreamWaitEvent(s2, evF, 0);

    cudaMemsetAsync(cntp, 0, (size_t)n * sizeof(int), s2);
    int et = (e + 3) / 4;
    hist_kernel<<<(et + 255) / 256, 256, 0, s2>>>(ei, e);
    int nb = (n + 255) / 256;
    scan1_kernel<<<nb, 256, 0, s2>>>(n);
    scan2_kernel<<<1, 1024, 0, s2>>>(nb);
    scan3_kernel<<<nb, 256, 0, s2>>>(n);
    fill_kernel<<<(et + 255) / 256, 256, 0, s2>>>(ei, e);
    cudaEventRecord(evJ, s2);

    // main stream: fp16 tensor GEMM + attention projections
    gemm_f16<<<(n + 127) / 128, 256>>>(x, Wt, n);
    int at = n * NHEAD;
    alpha_kernel<<<(at + 255) / 256, 256>>>(Watt, batt, n);

    // join, then fused gather + softmax + normalize
    cudaStreamWaitEvent(0, evJ, 0);
    long long threads = (long long)n * 32;
    gather_kernel<<<(unsigned)((threads + 255) / 256), 256>>>(out, n);
}

// round 8
// speedup vs baseline: 2.6837x; 1.0496x over previous
#include <cuda_runtime.h>
#include <cuda_fp16.h>
#include <cstdint>

#define DIN  256
#define DOUT 128
#define NHEAD 8
#define DH   16

#define MAX_N 50000
#define MAX_E 800000

__device__ __half g_h16[MAX_N * DOUT];
__device__ float g_alpha_src[MAX_N * NHEAD];
__device__ float g_alpha_dst[MAX_N * NHEAD];
__device__ int   g_cnt[MAX_N];
__device__ int   g_row[MAX_N];
__device__ int   g_adj[MAX_E];
__device__ int   g_pos[MAX_E];
__device__ int   g_bsum[1024];

#define MMA_F16(C, A, B)                                                      \
    asm volatile("mma.sync.aligned.m16n8k16.row.col.f32.f16.f16.f32 "         \
                 "{%0,%1,%2,%3}, {%4,%5,%6,%7}, {%8,%9}, {%0,%1,%2,%3};"      \
                 : "+f"((C)[0]), "+f"((C)[1]), "+f"((C)[2]), "+f"((C)[3])     \
                 : "r"((A)[0]), "r"((A)[1]), "r"((A)[2]), "r"((A)[3]),        \
                   "r"((B)[0]), "r"((B)[1]))

// ---------------------------------------------------------------------------
// fp16 GEMM (NT), fp32 accumulate, with FUSED attention-projection epilogue.
// g_h16[m,n] = sum_k A[m,k]*B[n,k];  alpha_src/dst computed from fp32 accum.
// Block 128x128, K-tile 32, 8 warps (2M x 4N), warp tile 64x32.
// ---------------------------------------------------------------------------
#define KT 32
#define ROWP 40
__global__ __launch_bounds__(256) void gemm_f16(const float* __restrict__ A,
                                                const float* __restrict__ B,
                                                const float* __restrict__ Watt,
                                                const float* __restrict__ batt,
                                                int M) {
    __shared__ __half As[128][ROWP];
    __shared__ __half Bs[128][ROWP];

    int tid = threadIdx.x;
    int blockRow = blockIdx.x * 128;
    int warpId = tid >> 5, lane = tid & 31;
    int g = lane >> 2, tig = lane & 3;
    int mBase = (warpId & 1) * 64;
    int nBase = (warpId >> 1) * 32;

    float c[4][4][4];
    #pragma unroll
    for (int mt = 0; mt < 4; mt++)
        #pragma unroll
        for (int nt = 0; nt < 4; nt++)
            #pragma unroll
            for (int r = 0; r < 4; r++) c[mt][nt][r] = 0.f;

    int lm = tid & 127;
    int lk = (tid >> 7) * 16;    // 0 or 16
    int gm = blockRow + lm;
    if (gm > M - 1) gm = M - 1;

    float4 pa[4], pb[4];
    #pragma unroll
    for (int q = 0; q < 4; q++) {
        pa[q] = *reinterpret_cast<const float4*>(&A[(size_t)gm * DIN + lk + q * 4]);
        pb[q] = *reinterpret_cast<const float4*>(&B[(size_t)lm * DIN + lk + q * 4]);
    }

    for (int t = 0; t < DIN / KT; t++) {
        #pragma unroll
        for (int q = 0; q < 4; q++) {
            __half2* ap = reinterpret_cast<__half2*>(&As[lm][lk + q * 4]);
            __half2* bp = reinterpret_cast<__half2*>(&Bs[lm][lk + q * 4]);
            ap[0] = __floats2half2_rn(pa[q].x, pa[q].y);
            ap[1] = __floats2half2_rn(pa[q].z, pa[q].w);
            bp[0] = __floats2half2_rn(pb[q].x, pb[q].y);
            bp[1] = __floats2half2_rn(pb[q].z, pb[q].w);
        }
        __syncthreads();

        if (t + 1 < DIN / KT) {
            int k0 = (t + 1) * KT;
            #pragma unroll
            for (int q = 0; q < 4; q++) {
                pa[q] = *reinterpret_cast<const float4*>(&A[(size_t)gm * DIN + k0 + lk + q * 4]);
                pb[q] = *reinterpret_cast<const float4*>(&B[(size_t)lm * DIN + k0 + lk + q * 4]);
            }
        }

        #pragma unroll
        for (int kk = 0; kk < KT; kk += 16) {
            int kh = (kk >> 1) + tig;
            uint32_t a_fr[4][4], b_fr[4][2];
            #pragma unroll
            for (int mt = 0; mt < 4; mt++) {
                int m0 = mBase + mt * 16 + g;
                const __half2* r0 = reinterpret_cast<const __half2*>(&As[m0][0]);
                const __half2* r1 = reinterpret_cast<const __half2*>(&As[m0 + 8][0]);
                a_fr[mt][0] = *reinterpret_cast<const uint32_t*>(&r0[kh]);
                a_fr[mt][1] = *reinterpret_cast<const uint32_t*>(&r1[kh]);
                a_fr[mt][2] = *reinterpret_cast<const uint32_t*>(&r0[kh + 4]);
                a_fr[mt][3] = *reinterpret_cast<const uint32_t*>(&r1[kh + 4]);
            }
            #pragma unroll
            for (int nt = 0; nt < 4; nt++) {
                int n0 = nBase + nt * 8 + g;
                const __half2* rb = reinterpret_cast<const __half2*>(&Bs[n0][0]);
                b_fr[nt][0] = *reinterpret_cast<const uint32_t*>(&rb[kh]);
                b_fr[nt][1] = *reinterpret_cast<const uint32_t*>(&rb[kh + 4]);
            }
            #pragma unroll
            for (int mt = 0; mt < 4; mt++)
                #pragma unroll
                for (int nt = 0; nt < 4; nt++)
                    MMA_F16(c[mt][nt], a_fr[mt], b_fr[nt]);
        }
        __syncthreads();
    }

    // store h as fp16
    #pragma unroll
    for (int mt = 0; mt < 4; mt++) {
        int row0 = blockRow + mBase + mt * 16 + g;
        int row1 = row0 + 8;
        #pragma unroll
        for (int nt = 0; nt < 4; nt++) {
            int col = nBase + nt * 8 + tig * 2;
            if (row0 < M)
                *reinterpret_cast<__half2*>(&g_h16[(size_t)row0 * DOUT + col]) =
                    __floats2half2_rn(c[mt][nt][0], c[mt][nt][1]);
            if (row1 < M)
                *reinterpret_cast<__half2*>(&g_h16[(size_t)row1 * DOUT + col]) =
                    __floats2half2_rn(c[mt][nt][2], c[mt][nt][3]);
        }
    }

    // fused alpha epilogue: per (row, head) dot with W_att, reduced over tig quad
    float bb = batt[0];
    float wa[2][2], wb[2][2];     // [q][0/1] within-head cols q*8+tig*2(+1)
    #pragma unroll
    for (int q = 0; q < 2; q++) {
        int j = q * 8 + tig * 2;
        wa[q][0] = Watt[j];       wa[q][1] = Watt[j + 1];
        wb[q][0] = Watt[16 + j];  wb[q][1] = Watt[16 + j + 1];
    }
    int headBase = nBase >> 4;
    #pragma unroll
    for (int mt = 0; mt < 4; mt++) {
        #pragma unroll
        for (int r = 0; r < 2; r++) {
            int row = blockRow + mBase + mt * 16 + g + r * 8;
            #pragma unroll
            for (int hl = 0; hl < 2; hl++) {
                float sa = 0.f, sb = 0.f;
                #pragma unroll
                for (int q = 0; q < 2; q++) {
                    int nt = 2 * hl + q;
                    float c0 = c[mt][nt][r * 2 + 0];
                    float c1 = c[mt][nt][r * 2 + 1];
                    sa += c0 * wa[q][0] + c1 * wa[q][1];
                    sb += c0 * wb[q][0] + c1 * wb[q][1];
                }
                sa += __shfl_xor_sync(0xffffffffu, sa, 1);
                sa += __shfl_xor_sync(0xffffffffu, sa, 2);
                sb += __shfl_xor_sync(0xffffffffu, sb, 1);
                sb += __shfl_xor_sync(0xffffffffu, sb, 2);
                if (tig == 0 && row < M) {
                    int head = headBase + hl;
                    g_alpha_src[row * NHEAD + head] = sa;
                    g_alpha_dst[row * NHEAD + head] = sb + bb;
                }
            }
        }
    }
}

// ---------------------------------------------------------------------------
// CSR build
// ---------------------------------------------------------------------------
__global__ void hist_kernel(const int* __restrict__ ei, int e) {
    int i0 = (blockIdx.x * blockDim.x + threadIdx.x) * 8;
    if (((e & 7) == 0) && i0 + 7 < e) {
        int4 d0 = *reinterpret_cast<const int4*>(&ei[e + i0]);
        int4 d1 = *reinterpret_cast<const int4*>(&ei[e + i0 + 4]);
        int4 p0, p1;
        p0.x = atomicAdd(&g_cnt[d0.x], 1);
        p0.y = atomicAdd(&g_cnt[d0.y], 1);
        p0.z = atomicAdd(&g_cnt[d0.z], 1);
        p0.w = atomicAdd(&g_cnt[d0.w], 1);
        p1.x = atomicAdd(&g_cnt[d1.x], 1);
        p1.y = atomicAdd(&g_cnt[d1.y], 1);
        p1.z = atomicAdd(&g_cnt[d1.z], 1);
        p1.w = atomicAdd(&g_cnt[d1.w], 1);
        *reinterpret_cast<int4*>(&g_pos[i0])     = p0;
        *reinterpret_cast<int4*>(&g_pos[i0 + 4]) = p1;
    } else {
        for (int i = i0; i < e && i < i0 + 8; i++)
            g_pos[i] = atomicAdd(&g_cnt[ei[e + i]], 1);
    }
}

__global__ __launch_bounds__(256) void scan1_kernel(int n) {
    __shared__ int ws[8];
    int i = blockIdx.x * 256 + threadIdx.x;
    int v = (i < n) ? g_cnt[i] : 0;
    int lane = threadIdx.x & 31, wid = threadIdx.x >> 5;
    int s = v;
    #pragma unroll
    for (int o = 16; o > 0; o >>= 1) s += __shfl_down_sync(0xffffffffu, s, o);
    if (lane == 0) ws[wid] = s;
    __syncthreads();
    if (threadIdx.x == 0) {
        int t = 0;
        #pragma unroll
        for (int w = 0; w < 8; w++) t += ws[w];
        g_bsum[blockIdx.x] = t;
    }
}

// merged scan: each block computes its own offset from g_bsum, then local scan
__global__ __launch_bounds__(256) void scan23_kernel(int n) {
    __shared__ int ws[8];
    __shared__ int boff;
    int lane = threadIdx.x & 31, wid = threadIdx.x >> 5;

    if (wid == 0) {
        int s = 0;
        for (int j = lane; j < blockIdx.x; j += 32) s += g_bsum[j];
        #pragma unroll
        for (int o = 16; o > 0; o >>= 1) s += __shfl_down_sync(0xffffffffu, s, o);
        if (lane == 0) boff = s;
    }

    int i = blockIdx.x * 256 + threadIdx.x;
    int v = (i < n) ? g_cnt[i] : 0;
    int x = v;
    #pragma unroll
    for (int o = 1; o < 32; o <<= 1) {
        int y = __shfl_up_sync(0xffffffffu, x, o);
        if (lane >= o) x += y;
    }
    if (lane == 31) ws[wid] = x;
    __syncthreads();
    if (wid == 0 && lane < 8) {
        int s = ws[lane];
        #pragma unroll
        for (int o = 1; o < 8; o <<= 1) {
            int y = __shfl_up_sync(0xffu, s, o);
            if (lane >= o) s += y;
        }
        ws[lane] = s;
    }
    __syncthreads();
    int excl = x - v + ((wid > 0) ? ws[wid - 1] : 0) + boff;
    if (i < n) g_row[i] = excl;
}

__global__ void fill_kernel(const int* __restrict__ ei, int e) {
    int i0 = (blockIdx.x * blockDim.x + threadIdx.x) * 8;
    if (((e & 7) == 0) && i0 + 7 < e) {
        int4 s0 = *reinterpret_cast<const int4*>(&ei[i0]);
        int4 s1 = *reinterpret_cast<const int4*>(&ei[i0 + 4]);
        int4 d0 = *reinterpret_cast<const int4*>(&ei[e + i0]);
        int4 d1 = *reinterpret_cast<const int4*>(&ei[e + i0 + 4]);
        int4 p0 = *reinterpret_cast<const int4*>(&g_pos[i0]);
        int4 p1 = *reinterpret_cast<const int4*>(&g_pos[i0 + 4]);
        g_adj[g_row[d0.x] + p0.x] = s0.x;
        g_adj[g_row[d0.y] + p0.y] = s0.y;
        g_adj[g_row[d0.z] + p0.z] = s0.z;
        g_adj[g_row[d0.w] + p0.w] = s0.w;
        g_adj[g_row[d1.x] + p1.x] = s1.x;
        g_adj[g_row[d1.y] + p1.y] = s1.y;
        g_adj[g_row[d1.z] + p1.z] = s1.z;
        g_adj[g_row[d1.w] + p1.w] = s1.w;
    } else {
        for (int i = i0; i < e && i < i0 + 8; i++)
            g_adj[g_row[ei[e + i]] + g_pos[i]] = ei[i];
    }
}

// ---------------------------------------------------------------------------
// Gather: warp per dst node; fp16 h rows, fp32 accumulation, no atomics
// ---------------------------------------------------------------------------
__global__ __launch_bounds__(256) void gather_kernel(float* __restrict__ out, int n) {
    int w = (blockIdx.x * blockDim.x + threadIdx.x) >> 5;
    if (w >= n) return;
    int lane = threadIdx.x & 31;
    int head = lane >> 2;

    int start = g_row[w];
    int deg   = g_cnt[w];
    float adst = g_alpha_dst[w * NHEAD + head];

    float s0 = g_alpha_src[w * NHEAD + head] + adst;
    s0 = (s0 >= 0.f) ? s0 : 0.2f * s0;
    float ev = __expf(s0);
    float denom = ev;

    const __half2* hp = reinterpret_cast<const __half2*>(
        &g_h16[(size_t)w * DOUT + lane * 4]);
    float2 f0 = __half22float2(hp[0]);
    float2 f1 = __half22float2(hp[1]);
    float4 acc = make_float4(f0.x * ev, f0.y * ev, f1.x * ev, f1.y * ev);

    #pragma unroll 4
    for (int j = 0; j < deg; j++) {
        int src = __ldg(&g_adj[start + j]);
        float s = g_alpha_src[src * NHEAD + head] + adst;
        s = (s >= 0.f) ? s : 0.2f * s;
        float e2 = __expf(s);
        denom += e2;
        const __half2* vp = reinterpret_cast<const __half2*>(
            &g_h16[(size_t)src * DOUT + lane * 4]);
        float2 v0 = __half22float2(vp[0]);
        float2 v1 = __half22float2(vp[1]);
        acc.x += e2 * v0.x;
        acc.y += e2 * v0.y;
        acc.z += e2 * v1.x;
        acc.w += e2 * v1.y;
    }

    float inv = 1.f / denom;
    *reinterpret_cast<float4*>(&out[(size_t)w * DOUT + lane * 4]) =
        make_float4(acc.x * inv, acc.y * inv, acc.z * inv, acc.w * inv);
}

extern "C" void kernel_launch(void* const* d_in, const int* in_sizes, int n_in,
                              void* d_out, int out_size) {
    const float* x    = (const float*)d_in[0];
    const float* Wt   = (const float*)d_in[1];
    const float* Watt = (const float*)d_in[2];
    const float* batt = (const float*)d_in[3];
    const int*   ei   = (const int*)d_in[4];

    int n = in_sizes[0] / DIN;   // 50000
    int e = in_sizes[4] / 2;     // 800000
    float* out = (float*)d_out;

    static cudaStream_t s2 = nullptr;
    static cudaEvent_t evF = nullptr, evJ = nullptr;
    if (s2 == nullptr) {
        cudaStreamCreateWithFlags(&s2, cudaStreamNonBlocking);
        cudaEventCreateWithFlags(&evF, cudaEventDisableTiming);
        cudaEventCreateWithFlags(&evJ, cudaEventDisableTiming);
    }

    void* cntp = nullptr;
    cudaGetSymbolAddress(&cntp, g_cnt);

    // fork: CSR build on s2, concurrent with GEMM(+alpha) on main stream
    cudaEventRecord(evF, 0);
    cudaStreamWaitEvent(s2, evF, 0);

    cudaMemsetAsync(cntp, 0, (size_t)n * sizeof(int), s2);
    int et8 = (e + 7) / 8;
    hist_kernel<<<(et8 + 255) / 256, 256, 0, s2>>>(ei, e);
    int nb = (n + 255) / 256;
    scan1_kernel<<<nb, 256, 0, s2>>>(n);
    scan23_kernel<<<nb, 256, 0, s2>>>(n);
    fill_kernel<<<(et8 + 255) / 256, 256, 0, s2>>>(ei, e);
    cudaEventRecord(evJ, s2);

    // main stream: fp16 tensor GEMM with fused alpha epilogue
    gemm_f16<<<(n + 127) / 128, 256>>>(x, Wt, Watt, batt, n);

    // join, then fused gather + softmax + normalize
    cudaStreamWaitEvent(0, evJ, 0);
    long long threads = (long long)n * 32;
    gather_kernel<<<(unsigned)((threads + 255) / 256), 256>>>(out, n);
}